// round 1
// baseline (speedup 1.0000x reference)
#include <cuda_runtime.h>
#include <math.h>

#define Bn 8
#define C0 16
#define C1c 64
#define C2c 64
#define Tt 12
#define TP 10
#define T2 8
#define Nn 256
#define KTc 3
#define Hh 8
#define ALPHA 0.2f

// scratch (static device allocations — allowed)
__device__ float g_xg[Bn*TP*Nn*C1c];   // x_t1 in [b,t,n,c] layout
__device__ float g_xs[Bn*TP*Nn*C1c];   // x_t1 + gat accumulation -> x_s
__device__ int   g_deg[Nn];
__device__ int   g_nbr[Nn*Nn];
__device__ float g_lnwT[C2c*Nn];
__device__ float g_lnbT[C2c*Nn];

// ---------------------------------------------------------------------------
// Kernel A: conv1 (temporal, KT=3) + GLU. grid (TP, B), 256 threads (=n).
// smem: x window [48][256], packed weight pairs float4[64][24], transpose
// staging [64][257] for coalesced global writes.
// ---------------------------------------------------------------------------
__global__ void kA(const float* __restrict__ x,
                   const float* __restrict__ w1,
                   const float* __restrict__ b1) {
    extern __shared__ float sm[];
    float*  sx  = sm;                         // 48*256 = 12288
    float4* swp = (float4*)(sm + 48*256);     // 64*24 float4 = 6144 floats
    float*  sxt = sm + 48*256 + 64*24*4;      // 64*257 = 16448
    int tid = threadIdx.x;
    int t = blockIdx.x, b = blockIdx.y;

    for (int idx = tid; idx < 48*256; idx += 256) {
        int k = idx >> 8;          // cin*3 + kt
        int n = idx & 255;
        int cin = k / 3, kt = k % 3;
        sx[idx] = x[((b*C0 + cin)*Tt + t + kt)*Nn + n];
    }
    for (int idx = tid; idx < 64*24; idx += 256) {
        int c = idx / 24, k2 = idx % 24;
        float4 v;
        v.x = w1[c*48 + 2*k2];
        v.y = w1[c*48 + 2*k2 + 1];
        v.z = w1[(c+64)*48 + 2*k2];
        v.w = w1[(c+64)*48 + 2*k2 + 1];
        swp[idx] = v;
    }
    __syncthreads();

    int n = tid;
    float xr[48];
    #pragma unroll
    for (int k = 0; k < 48; k++) xr[k] = sx[k*256 + n];

    for (int c = 0; c < 64; c++) {
        float am = __ldg(b1 + c);
        float ag = __ldg(b1 + c + 64);
        #pragma unroll
        for (int k2 = 0; k2 < 24; k2++) {
            float4 w = swp[c*24 + k2];
            am = fmaf(xr[2*k2],   w.x, am);
            am = fmaf(xr[2*k2+1], w.y, am);
            ag = fmaf(xr[2*k2],   w.z, ag);
            ag = fmaf(xr[2*k2+1], w.w, ag);
        }
        // residual from padded input: x[b,c,t+2,n] for c < 16, else 0
        float xin = (c < C0) ? sx[(c*3 + 2)*256 + n] : 0.0f;
        float val = (am + xin) * (1.0f / (1.0f + __expf(-ag)));
        sxt[c*257 + n] = val;
    }
    __syncthreads();

    int base = ((b*TP + t)*Nn)*C1c;
    for (int idx = tid; idx < Nn*C1c; idx += 256) {
        int nn = idx >> 6, c = idx & 63;
        float v = sxt[c*257 + nn];
        g_xg[base + idx] = v;
        g_xs[base + idx] = v;   // gat accumulates on top -> becomes x_s
    }
}

// ---------------------------------------------------------------------------
// Kernel B: adjacency neighbor lists (self-loop guaranteed in adj) +
// transposed LayerNorm params. grid 1, 256 threads.
// ---------------------------------------------------------------------------
__global__ void kB(const float* __restrict__ adj,
                   const float* __restrict__ lnw,
                   const float* __restrict__ lnb) {
    int tid = threadIdx.x;
    if (tid < Nn) {
        int cnt = 0;
        for (int j = 0; j < Nn; j++)
            if (adj[tid*Nn + j] > 0.0f) g_nbr[tid*Nn + cnt++] = j;
        g_deg[tid] = cnt;
    }
    for (int idx = tid; idx < C2c*Nn; idx += 256) {
        int c = idx >> 8, n2 = idx & 255;
        g_lnwT[idx] = lnw[n2*C2c + c];
        g_lnbT[idx] = lnb[n2*C2c + c];
    }
}

// ---------------------------------------------------------------------------
// Kernel C: GAT head. grid (H, TP, B), 256 threads (8 warps, warp-per-row).
// smem: xg slice [256][65] (padded), e1/e2, v1/v2, per-warp score stash.
// ---------------------------------------------------------------------------
__global__ void kC(const float* __restrict__ Wh, const float* __restrict__ ah) {
    extern __shared__ float sm[];
    float* sxg = sm;                 // 256*65 = 16640
    float* se1 = sxg + 256*65;       // 256
    float* se2 = se1 + 256;          // 256
    float* sv1 = se2 + 256;          // 64
    float* sv2 = sv1 + 64;           // 64
    float* pw  = sv2 + 64;           // 8*256 = 2048
    int tid = threadIdx.x;
    int h = blockIdx.x, t = blockIdx.y, b = blockIdx.z;
    int base = ((b*TP + t)*Nn)*C1c;

    for (int idx = tid; idx < Nn*C1c; idx += 256) {
        int n = idx >> 6, c = idx & 63;
        sxg[n*65 + c] = g_xg[base + idx];
    }
    // v1[c] = sum_d W[h,c,d]*a1[h,d],  v2[c] = sum_d W[h,c,d]*a2[h,d]
    if (tid < 64) {
        float s = 0.0f;
        const float* wr = Wh + (h*64 + tid)*64;
        const float* ar = ah + h*128;
        #pragma unroll
        for (int d = 0; d < 64; d++) s = fmaf(wr[d], ar[d], s);
        sv1[tid] = s;
    } else if (tid < 128) {
        int c = tid - 64;
        float s = 0.0f;
        const float* wr = Wh + (h*64 + c)*64;
        const float* ar = ah + h*128 + 64;
        #pragma unroll
        for (int d = 0; d < 64; d++) s = fmaf(wr[d], ar[d], s);
        sv2[c] = s;
    }
    __syncthreads();
    {
        int n = tid;
        float s1 = 0.0f, s2 = 0.0f;
        #pragma unroll
        for (int c = 0; c < 64; c++) {
            float xv = sxg[n*65 + c];          // stride 65 -> conflict-free
            s1 = fmaf(xv, sv1[c], s1);
            s2 = fmaf(xv, sv2[c], s2);
        }
        se1[n] = s1; se2[n] = s2;
    }
    __syncthreads();

    int w = tid >> 5, lane = tid & 31;
    float* pwr = pw + w*256;
    for (int rr = 0; rr < 32; rr++) {
        int i = w*32 + rr;
        int d = g_deg[i];
        const int* nb = g_nbr + i*Nn;
        float ei = se1[i];

        float m = -1e30f;
        for (int k = lane; k < d; k += 32) {
            int j = nb[k];
            float s = ei + se2[j];
            s = (s > 0.0f) ? s : ALPHA * s;    // leaky_relu
            pwr[k] = s;
            m = fmaxf(m, s);
        }
        #pragma unroll
        for (int o = 16; o > 0; o >>= 1) m = fmaxf(m, __shfl_xor_sync(0xffffffffu, m, o));
        float ss = 0.0f;
        for (int k = lane; k < d; k += 32) {
            float p = __expf(pwr[k] - m);
            pwr[k] = p;
            ss += p;
        }
        #pragma unroll
        for (int o = 16; o > 0; o >>= 1) ss += __shfl_xor_sync(0xffffffffu, ss, o);
        __syncwarp();

        float a0 = 0.0f, a1 = 0.0f;
        int c0 = lane, c1 = lane + 32;
        int j = (d > 0) ? nb[0] : 0;
        for (int k = 0; k < d; k++) {
            int jn = (k + 1 < d) ? __ldg(nb + k + 1) : 0;
            float p = pwr[k];
            a0 = fmaf(p, sxg[j*65 + c0], a0);
            a1 = fmaf(p, sxg[j*65 + c1], a1);
            j = jn;
        }
        float r = 1.0f / ss;
        atomicAdd(&g_xs[base + i*64 + c0], tanhf(a0 * r) * (1.0f/Hh));
        atomicAdd(&g_xs[base + i*64 + c1], tanhf(a1 * r) * (1.0f/Hh));
        __syncwarp();   // pwr reused next row
    }
}

// ---------------------------------------------------------------------------
// Kernel D: conv2 + residual + ReLU + LayerNorm over (N,C). grid (T2, B),
// 256 threads (=n), acc[64] per thread. 4 input-channel chunks of 16.
// ---------------------------------------------------------------------------
__global__ void kD(const float* __restrict__ w2, const float* __restrict__ b2,
                   float* __restrict__ out) {
    extern __shared__ float sm[];
    float* sx2 = sm;               // 3*256*17 = 13056 (padded)
    float* sw2 = sm + 13056;       // 48*64 = 3072 (16B aligned: 52224 bytes)
    __shared__ float red[64];
    int tid = threadIdx.x;
    int t2 = blockIdx.x, b = blockIdx.y;
    int n = tid;

    float acc[64];
    #pragma unroll
    for (int c = 0; c < 64; c++) acc[c] = __ldg(b2 + c);

    #pragma unroll
    for (int g = 0; g < 4; g++) {
        __syncthreads();
        for (int idx = tid; idx < 16*3*256; idx += 256) {
            int ci = idx & 15;
            int nn = (idx >> 4) & 255;
            int kt = idx >> 12;
            sx2[(kt*256 + nn)*17 + ci] =
                g_xs[((b*TP + t2 + kt)*Nn + nn)*C1c + g*16 + ci];
        }
        for (int idx = tid; idx < 48*64; idx += 256) {
            int cout = idx & 63;
            int ck = idx >> 6;               // ci*3 + kt
            int ci = ck / 3, kt = ck % 3;
            sw2[ck*64 + cout] = w2[cout*(C1c*KTc) + (g*16 + ci)*KTc + kt];
        }
        __syncthreads();

        for (int ci = 0; ci < 16; ci++) {
            #pragma unroll
            for (int kt = 0; kt < 3; kt++) {
                float xv = sx2[(kt*256 + n)*17 + ci];
                const float4* wr = (const float4*)(sw2 + (ci*3 + kt)*64);
                #pragma unroll
                for (int q = 0; q < 16; q++) {
                    float4 wv = wr[q];               // broadcast LDS128
                    acc[q*4+0] = fmaf(xv, wv.x, acc[q*4+0]);
                    acc[q*4+1] = fmaf(xv, wv.y, acc[q*4+1]);
                    acc[q*4+2] = fmaf(xv, wv.z, acc[q*4+2]);
                    acc[q*4+3] = fmaf(xv, wv.w, acc[q*4+3]);
                }
            }
        }
        // residual x_s[b, cout, t2+2, n] for couts in this chunk
        #pragma unroll
        for (int cc = 0; cc < 16; cc++)
            acc[g*16 + cc] += sx2[(2*256 + n)*17 + cc];
    }

    float ls = 0.0f, lss = 0.0f;
    #pragma unroll
    for (int c = 0; c < 64; c++) {
        float v = fmaxf(acc[c], 0.0f);
        acc[c] = v;
        ls += v;
        lss = fmaf(v, v, lss);
    }
    #pragma unroll
    for (int o = 16; o > 0; o >>= 1) {
        ls  += __shfl_xor_sync(0xffffffffu, ls,  o);
        lss += __shfl_xor_sync(0xffffffffu, lss, o);
    }
    int w = tid >> 5, lane = tid & 31;
    if (lane == 0) { red[w] = ls; red[w + 8] = lss; }
    __syncthreads();
    if (tid == 0) {
        float S = 0.0f, SS = 0.0f;
        #pragma unroll
        for (int i = 0; i < 8; i++) { S += red[i]; SS += red[i + 8]; }
        red[16] = S; red[17] = SS;
    }
    __syncthreads();
    float mu   = red[16] * (1.0f/16384.0f);
    float var  = red[17] * (1.0f/16384.0f) - mu*mu;
    float rstd = rsqrtf(var + 1e-5f);

    #pragma unroll
    for (int c = 0; c < 64; c++) {
        float yv = (acc[c] - mu) * rstd;
        out[((b*C2c + c)*T2 + t2)*Nn + n] =
            fmaf(yv, g_lnwT[c*256 + n], g_lnbT[c*256 + n]);
    }
}

// ---------------------------------------------------------------------------
extern "C" void kernel_launch(void* const* d_in, const int* in_sizes, int n_in,
                              void* d_out, int out_size) {
    const float* x   = (const float*)d_in[0];
    const float* adj = (const float*)d_in[1];
    const float* w1  = (const float*)d_in[2];
    const float* b1  = (const float*)d_in[3];
    const float* w2  = (const float*)d_in[4];
    const float* b2  = (const float*)d_in[5];
    const float* Wh  = (const float*)d_in[6];
    const float* ah  = (const float*)d_in[7];
    const float* lnw = (const float*)d_in[8];
    const float* lnb = (const float*)d_in[9];
    float* out = (float*)d_out;

    const int smA = (48*256 + 64*24*4 + 64*257) * 4;   // 139520
    const int smC = (256*65 + 256 + 256 + 64 + 64 + 8*256) * 4;  // 77312
    const int smD = (13056 + 3072) * 4;                // 64512
    cudaFuncSetAttribute(kA, cudaFuncAttributeMaxDynamicSharedMemorySize, smA);
    cudaFuncSetAttribute(kC, cudaFuncAttributeMaxDynamicSharedMemorySize, smC);
    cudaFuncSetAttribute(kD, cudaFuncAttributeMaxDynamicSharedMemorySize, smD);

    kA<<<dim3(TP, Bn), 256, smA>>>(x, w1, b1);
    kB<<<1, 256>>>(adj, lnw, lnb);
    kC<<<dim3(Hh, TP, Bn), 256, smC>>>(Wh, ah);
    kD<<<dim3(T2, Bn), 256, smD>>>(w2, b2, out);
}

// round 2
// speedup vs baseline: 1.0985x; 1.0985x over previous
#include <cuda_runtime.h>
#include <math.h>

#define Bn 8
#define C0 16
#define C1c 64
#define C2c 64
#define Tt 12
#define TP 10
#define T2 8
#define Nn 256
#define KTc 3
#define Hh 8
#define ALPHA 0.2f
#define XSZ (Bn*TP*Nn*C1c)   // 1310720

// scratch (static device allocations — allowed)
__device__ float g_xg[XSZ];        // x_t1 in [b,t,n,c]
__device__ float g_xs[XSZ];        // x_t1 + gat -> x_s
__device__ float g_hd[4*XSZ];      // per-head-pair gat partials
__device__ float g_y[Bn*T2*C2c*Nn];// conv2+relu output, [bt][c][n]
__device__ float g_psum[Bn*T2*4*2];// per (bt, cs) partial sums
__device__ int   g_deg[Nn];
__device__ int   g_nbr[Nn*Nn];
__device__ float g_lnwT[C2c*Nn];
__device__ float g_lnbT[C2c*Nn];

// ---------------------------------------------------------------------------
// Kernel A: conv1 (KT=3) + GLU. grid (2, TP, B), 128 threads (n-split).
// smem: region reused for x-window then transpose staging; packed w pairs.
// ---------------------------------------------------------------------------
__global__ void kA(const float* __restrict__ x,
                   const float* __restrict__ w1,
                   const float* __restrict__ b1) {
    extern __shared__ float sm[];
    float*  sx  = sm;                       // 48*128 = 6144 (then reused)
    float*  sxt = sm;                       // 64*129 = 8256 (overlaps sx)
    float4* swp = (float4*)(sm + 8256);     // 64*24 float4 = 6144 floats
    int tid = threadIdx.x;
    int half = blockIdx.x, t = blockIdx.y, b = blockIdx.z;
    int n0 = half * 128;

    for (int idx = tid; idx < 48*128; idx += 128) {
        int k = idx >> 7;          // cin*3 + kt
        int nl = idx & 127;
        int cin = k / 3, kt = k % 3;
        sx[idx] = x[((b*C0 + cin)*Tt + t + kt)*Nn + n0 + nl];
    }
    for (int idx = tid; idx < 64*24; idx += 128) {
        int c = idx / 24, k2 = idx % 24;
        float4 v;
        v.x = w1[c*48 + 2*k2];
        v.y = w1[c*48 + 2*k2 + 1];
        v.z = w1[(c+64)*48 + 2*k2];
        v.w = w1[(c+64)*48 + 2*k2 + 1];
        swp[idx] = v;
    }
    __syncthreads();

    int nl = tid;
    float xr[48];
    #pragma unroll
    for (int k = 0; k < 48; k++) xr[k] = sx[k*128 + nl];
    __syncthreads();   // sx region about to be reused as sxt

    for (int c = 0; c < 64; c++) {
        float am = __ldg(b1 + c);
        float ag = __ldg(b1 + c + 64);
        #pragma unroll
        for (int k2 = 0; k2 < 24; k2++) {
            float4 w = swp[c*24 + k2];
            am = fmaf(xr[2*k2],   w.x, am);
            am = fmaf(xr[2*k2+1], w.y, am);
            ag = fmaf(xr[2*k2],   w.z, ag);
            ag = fmaf(xr[2*k2+1], w.w, ag);
        }
        float xin = (c < C0) ? xr[c*3 + 2] : 0.0f;
        float val = (am + xin) * (1.0f / (1.0f + __expf(-ag)));
        sxt[c*129 + nl] = val;
    }
    __syncthreads();

    int base = ((b*TP + t)*Nn + n0)*C1c;
    for (int idx = tid; idx < 128*C1c; idx += 128) {
        int nn = idx >> 6, c = idx & 63;
        g_xg[base + idx] = sxt[c*129 + nn];
    }
}

// ---------------------------------------------------------------------------
// Kernel B: adjacency neighbor lists + transposed LN params. grid 1, 256 thr.
// ---------------------------------------------------------------------------
__global__ void kB(const float* __restrict__ adj,
                   const float* __restrict__ lnw,
                   const float* __restrict__ lnb) {
    int tid = threadIdx.x;
    if (tid < Nn) {
        int cnt = 0;
        for (int j = 0; j < Nn; j++)
            if (adj[tid*Nn + j] > 0.0f) g_nbr[tid*Nn + cnt++] = j;
        g_deg[tid] = cnt;
    }
    for (int idx = tid; idx < C2c*Nn; idx += 256) {
        int c = idx >> 8, n2 = idx & 255;
        g_lnwT[idx] = lnw[n2*C2c + c];
        g_lnbT[idx] = lnb[n2*C2c + c];
    }
}

// ---------------------------------------------------------------------------
// Kernel C: GAT, 2 heads/block. grid (4, TP, B) = 320 blocks, 256 threads.
// smem: xg [256][66] (float2-friendly pad), e1/e2 per head, v per head,
// per-warp score+neighbor stash (LDG pointer-chase eliminated).
// ---------------------------------------------------------------------------
__global__ void kC(const float* __restrict__ Wh, const float* __restrict__ ah) {
    extern __shared__ float sm[];
    float* sxg = sm;                  // 256*66 = 16896
    float* se1 = sxg + 16896;         // 2*256
    float* se2 = se1 + 512;           // 2*256
    float* sv  = se2 + 512;           // 4*64  [h0v1,h0v2,h1v1,h1v2]
    float* pws = sv + 256;            // 8 warps * (96 pwr + 96 snb)
    int tid = threadIdx.x;
    int z = blockIdx.x, t = blockIdx.y, b = blockIdx.z;
    int h0 = 2*z;
    int base = ((b*TP + t)*Nn)*C1c;

    for (int idx = tid; idx < Nn*C1c/4; idx += 256) {
        float4 v = ((const float4*)(g_xg + base))[idx];
        int n2 = idx >> 4, cq = (idx & 15) * 4;
        float* p = sxg + n2*66 + cq;
        p[0] = v.x; p[1] = v.y; p[2] = v.z; p[3] = v.w;
    }
    {   // v vectors: which = tid>>6 : (head, a-half)
        int which = tid >> 6, c = tid & 63;
        int hh = which >> 1, halfa = which & 1;
        const float* wr = Wh + ((h0 + hh)*64 + c)*64;
        const float* ar = ah + (h0 + hh)*128 + halfa*64;
        float s = 0.0f;
        #pragma unroll
        for (int d2 = 0; d2 < 64; d2++) s = fmaf(wr[d2], ar[d2], s);
        sv[which*64 + c] = s;
    }
    __syncthreads();
    {   // e1,e2 for both heads
        int n2 = tid;
        float s10 = 0, s20 = 0, s11 = 0, s21 = 0;
        #pragma unroll
        for (int c = 0; c < 64; c++) {
            float xv = sxg[n2*66 + c];
            s10 = fmaf(xv, sv[c],       s10);
            s20 = fmaf(xv, sv[64 + c],  s20);
            s11 = fmaf(xv, sv[128 + c], s11);
            s21 = fmaf(xv, sv[192 + c], s21);
        }
        se1[n2] = s10; se2[n2] = s20;
        se1[256 + n2] = s11; se2[256 + n2] = s21;
    }
    __syncthreads();

    int w = tid >> 5, lane = tid & 31;
    float* pwr = pws + w*192;
    int*   snb = (int*)(pwr + 96);
    int c0 = 2*lane;

    for (int rr = 0; rr < 32; rr++) {
        int i = w*32 + rr;
        int d = g_deg[i]; if (d > 96) d = 96;
        const int* nb = g_nbr + i*Nn;
        for (int k = lane; k < d; k += 32) snb[k] = nb[k];
        __syncwarp();

        float2 acc = {0.0f, 0.0f};
        #pragma unroll
        for (int hh = 0; hh < 2; hh++) {
            float ei = se1[hh*256 + i];
            const float* se2h = se2 + hh*256;
            float m = -1e30f;
            for (int k = lane; k < d; k += 32) {
                int j = snb[k];
                float s = ei + se2h[j];
                s = (s > 0.0f) ? s : ALPHA * s;
                pwr[k] = s;
                m = fmaxf(m, s);
            }
            #pragma unroll
            for (int o = 16; o > 0; o >>= 1)
                m = fmaxf(m, __shfl_xor_sync(0xffffffffu, m, o));
            float ss = 0.0f;
            for (int k = lane; k < d; k += 32) {
                float p = __expf(pwr[k] - m);
                pwr[k] = p;
                ss += p;
            }
            #pragma unroll
            for (int o = 16; o > 0; o >>= 1)
                ss += __shfl_xor_sync(0xffffffffu, ss, o);
            __syncwarp();

            float a0 = 0, a1 = 0, b0 = 0, b1 = 0;   // dual accumulators
            int k = 0;
            for (; k + 1 < d; k += 2) {
                int ja = snb[k], jb = snb[k+1];
                float pa = pwr[k], pb = pwr[k+1];
                float2 xa = *(const float2*)&sxg[ja*66 + c0];
                float2 xb = *(const float2*)&sxg[jb*66 + c0];
                a0 = fmaf(pa, xa.x, a0); a1 = fmaf(pa, xa.y, a1);
                b0 = fmaf(pb, xb.x, b0); b1 = fmaf(pb, xb.y, b1);
            }
            if (k < d) {
                int j = snb[k]; float p = pwr[k];
                float2 xv = *(const float2*)&sxg[j*66 + c0];
                a0 = fmaf(p, xv.x, a0); a1 = fmaf(p, xv.y, a1);
            }
            float r = 1.0f / ss;
            acc.x += tanhf((a0 + b0) * r) * 0.125f;
            acc.y += tanhf((a1 + b1) * r) * 0.125f;
            __syncwarp();   // pwr reused by next head/row
        }
        *(float2*)&g_hd[z*XSZ + base + i*64 + c0] = acc;
    }
}

// ---------------------------------------------------------------------------
// Kernel S: x_s = x_t1 + sum of 4 head-pair partials. grid 1280 x 256, float4.
// ---------------------------------------------------------------------------
__global__ void kS() {
    int idx = blockIdx.x * 256 + threadIdx.x;
    float4 v = ((const float4*)g_xg)[idx];
    #pragma unroll
    for (int z = 0; z < 4; z++) {
        float4 h = ((const float4*)(g_hd + z*XSZ))[idx];
        v.x += h.x; v.y += h.y; v.z += h.z; v.w += h.w;
    }
    ((float4*)g_xs)[idx] = v;
}

// ---------------------------------------------------------------------------
// Kernel D1: conv2 + residual + relu + partial LN stats.
// grid (T2, B, 4 cout-chunks) = 256 blocks, 256 threads (n).
// ---------------------------------------------------------------------------
__global__ void kD1(const float* __restrict__ w2, const float* __restrict__ b2) {
    extern __shared__ float sm[];
    float* sx2 = sm;            // 3*256*17 = 13056
    float* sw2 = sm + 13056;    // 48*16 = 768
    __shared__ float red[16];
    int tid = threadIdx.x;
    int t2 = blockIdx.x, b = blockIdx.y, cs = blockIdx.z;
    int n = tid;

    float acc[16];
    #pragma unroll
    for (int cc = 0; cc < 16; cc++) acc[cc] = __ldg(b2 + cs*16 + cc);

    #pragma unroll
    for (int g = 0; g < 4; g++) {
        __syncthreads();
        for (int idx = tid; idx < 16*3*256; idx += 256) {
            int ci = idx & 15;
            int nn = (idx >> 4) & 255;
            int kt = idx >> 12;
            sx2[(kt*256 + nn)*17 + ci] =
                g_xs[((b*TP + t2 + kt)*Nn + nn)*C1c + g*16 + ci];
        }
        for (int idx = tid; idx < 48*16; idx += 256) {
            int cout = idx & 15;
            int ck = idx >> 4;               // ci*3 + kt
            int ci = ck / 3, kt = ck % 3;
            sw2[ck*16 + cout] = w2[(cs*16 + cout)*(C1c*KTc) + (g*16 + ci)*KTc + kt];
        }
        __syncthreads();

        for (int ci = 0; ci < 16; ci++) {
            #pragma unroll
            for (int kt = 0; kt < 3; kt++) {
                float xv = sx2[(kt*256 + n)*17 + ci];
                const float4* wr = (const float4*)(sw2 + (ci*3 + kt)*16);
                #pragma unroll
                for (int q = 0; q < 4; q++) {
                    float4 wv = wr[q];
                    acc[q*4+0] = fmaf(xv, wv.x, acc[q*4+0]);
                    acc[q*4+1] = fmaf(xv, wv.y, acc[q*4+1]);
                    acc[q*4+2] = fmaf(xv, wv.z, acc[q*4+2]);
                    acc[q*4+3] = fmaf(xv, wv.w, acc[q*4+3]);
                }
            }
        }
        if (g == cs) {
            #pragma unroll
            for (int cc = 0; cc < 16; cc++)
                acc[cc] += sx2[(2*256 + n)*17 + cc];
        }
    }

    float ls = 0.0f, lss = 0.0f;
    #pragma unroll
    for (int cc = 0; cc < 16; cc++) {
        float v = fmaxf(acc[cc], 0.0f);
        acc[cc] = v;
        ls += v;
        lss = fmaf(v, v, lss);
    }
    #pragma unroll
    for (int o = 16; o > 0; o >>= 1) {
        ls  += __shfl_xor_sync(0xffffffffu, ls,  o);
        lss += __shfl_xor_sync(0xffffffffu, lss, o);
    }
    int w = tid >> 5, lane = tid & 31;
    if (lane == 0) { red[w] = ls; red[w + 8] = lss; }
    __syncthreads();
    if (tid == 0) {
        float S = 0.0f, SS = 0.0f;
        #pragma unroll
        for (int i = 0; i < 8; i++) { S += red[i]; SS += red[i + 8]; }
        int bt = b*T2 + t2;
        g_psum[(bt*4 + cs)*2]     = S;
        g_psum[(bt*4 + cs)*2 + 1] = SS;
    }

    int ybase = ((b*T2 + t2)*C2c + cs*16)*Nn;
    #pragma unroll
    for (int cc = 0; cc < 16; cc++)
        g_y[ybase + cc*Nn + n] = acc[cc];
}

// ---------------------------------------------------------------------------
// Kernel E: LayerNorm + transposed store. grid (T2, B, 4), 256 threads.
// ---------------------------------------------------------------------------
__global__ void kE(float* __restrict__ out) {
    int t2 = blockIdx.x, b = blockIdx.y, cs = blockIdx.z;
    int bt = b*T2 + t2;
    float S = 0.0f, SS = 0.0f;
    #pragma unroll
    for (int q = 0; q < 4; q++) {
        S  += g_psum[(bt*4 + q)*2];
        SS += g_psum[(bt*4 + q)*2 + 1];
    }
    float mu   = S * (1.0f/16384.0f);
    float var  = SS * (1.0f/16384.0f) - mu*mu;
    float rstd = rsqrtf(var + 1e-5f);
    int n = threadIdx.x;
    #pragma unroll
    for (int cc = 0; cc < 16; cc++) {
        int c = cs*16 + cc;
        float yv = (g_y[(bt*C2c + c)*Nn + n] - mu) * rstd;
        out[((b*C2c + c)*T2 + t2)*Nn + n] =
            fmaf(yv, g_lnwT[c*Nn + n], g_lnbT[c*Nn + n]);
    }
}

// ---------------------------------------------------------------------------
extern "C" void kernel_launch(void* const* d_in, const int* in_sizes, int n_in,
                              void* d_out, int out_size) {
    const float* x   = (const float*)d_in[0];
    const float* adj = (const float*)d_in[1];
    const float* w1  = (const float*)d_in[2];
    const float* b1  = (const float*)d_in[3];
    const float* w2  = (const float*)d_in[4];
    const float* b2  = (const float*)d_in[5];
    const float* Wh  = (const float*)d_in[6];
    const float* ah  = (const float*)d_in[7];
    const float* lnw = (const float*)d_in[8];
    const float* lnb = (const float*)d_in[9];
    float* out = (float*)d_out;

    const int smA = (8256 + 6144) * 4;                         // 57600
    const int smC = (16896 + 512 + 512 + 256 + 8*192) * 4;     // 78848
    const int smD = (13056 + 768) * 4;                         // 55296
    cudaFuncSetAttribute(kA,  cudaFuncAttributeMaxDynamicSharedMemorySize, smA);
    cudaFuncSetAttribute(kC,  cudaFuncAttributeMaxDynamicSharedMemorySize, smC);
    cudaFuncSetAttribute(kD1, cudaFuncAttributeMaxDynamicSharedMemorySize, smD);

    kA<<<dim3(2, TP, Bn), 128, smA>>>(x, w1, b1);
    kB<<<1, 256>>>(adj, lnw, lnb);
    kC<<<dim3(4, TP, Bn), 256, smC>>>(Wh, ah);
    kS<<<XSZ/4/256, 256>>>();
    kD1<<<dim3(T2, Bn, 4), 256, smD>>>(w2, b2);
    kE<<<dim3(T2, Bn, 4), 256>>>(out);
}

// round 3
// speedup vs baseline: 1.9035x; 1.7328x over previous
#include <cuda_runtime.h>
#include <math.h>

#define Bn 8
#define C0 16
#define C1c 64
#define C2c 64
#define Tt 12
#define TP 10
#define T2 8
#define Nn 256
#define KTc 3
#define Hh 8
#define ALPHA 0.2f
#define DMAX 96
#define XSZ (Bn*TP*Nn*C1c)   // 1310720

// scratch (static device allocations — allowed)
__device__ float g_xg[XSZ];          // x_t1 in [b,t,n,c]
__device__ float g_xs[XSZ];          // x_t1 + gat -> x_s
__device__ float g_y[Bn*T2*C2c*Nn];  // conv2+relu output, [bt][c][n]
__device__ float g_psum[Bn*T2*4*2];  // per (bt, cs) partial LN sums
__device__ int   g_deg[Nn];
__device__ int   g_nbr[Nn*DMAX];
__device__ float g_v[16*64];         // v[(h*2+half)*64 + c]
__device__ float g_lnwT[C2c*Nn];
__device__ float g_lnbT[C2c*Nn];

__device__ __forceinline__ float tanh_ap(float x) {
    float y;
    asm("tanh.approx.f32 %0, %1;" : "=f"(y) : "f"(x));
    return y;
}

// ---------------------------------------------------------------------------
// Kernel A: conv1 (KT=3) + GLU. grid (4, TP, B): quadrant = (n-half, c-half).
// 128 threads. smem: x window (reused as transpose staging) + packed weights.
// ---------------------------------------------------------------------------
__global__ void kA(const float* __restrict__ x,
                   const float* __restrict__ w1,
                   const float* __restrict__ b1) {
    extern __shared__ float sm[];
    float*  sx  = sm;                       // 48*128 = 6144 (reused as sxt 32*129=4128)
    float4* swp = (float4*)(sm + 6144);     // 32*24 float4 = 3072 floats
    int tid = threadIdx.x;
    int q = blockIdx.x, t = blockIdx.y, b = blockIdx.z;
    int nh = q & 1, ch = q >> 1;
    int n0 = nh * 128;

    for (int idx = tid; idx < 48*128; idx += 128) {
        int k = idx >> 7;          // cin*3 + kt
        int nl = idx & 127;
        int cin = k / 3, kt = k % 3;
        sx[idx] = x[((b*C0 + cin)*Tt + t + kt)*Nn + n0 + nl];
    }
    for (int idx = tid; idx < 32*24; idx += 128) {
        int cl = idx / 24, k2 = idx % 24;
        int c = ch*32 + cl;
        float4 v;
        v.x = w1[c*48 + 2*k2];
        v.y = w1[c*48 + 2*k2 + 1];
        v.z = w1[(c+64)*48 + 2*k2];
        v.w = w1[(c+64)*48 + 2*k2 + 1];
        swp[idx] = v;
    }
    __syncthreads();

    int nl = tid;
    float xr[48];
    #pragma unroll
    for (int k = 0; k < 48; k++) xr[k] = sx[k*128 + nl];
    __syncthreads();   // sx reused as sxt below

    for (int cl = 0; cl < 32; cl++) {
        int c = ch*32 + cl;
        float am = __ldg(b1 + c);
        float ag = __ldg(b1 + c + 64);
        #pragma unroll
        for (int k2 = 0; k2 < 24; k2++) {
            float4 w = swp[cl*24 + k2];
            am = fmaf(xr[2*k2],   w.x, am);
            am = fmaf(xr[2*k2+1], w.y, am);
            ag = fmaf(xr[2*k2],   w.z, ag);
            ag = fmaf(xr[2*k2+1], w.w, ag);
        }
        float xin = (c < C0) ? xr[c*3 + 2] : 0.0f;
        float val = (am + xin) * (1.0f / (1.0f + __expf(-ag)));
        sx[cl*129 + nl] = val;
    }
    __syncthreads();

    int base = ((b*TP + t)*Nn + n0)*C1c + ch*32;
    for (int idx = tid; idx < 128*32; idx += 128) {
        int n2 = idx >> 5, cl = idx & 31;
        g_xg[base + n2*64 + cl] = sx[cl*129 + n2];
    }
}

// ---------------------------------------------------------------------------
// Kernel B: ballot-compacted adjacency lists + v vectors + transposed LN
// params. grid 1, 256 threads (8 warps x 32 rows each).
// ---------------------------------------------------------------------------
__global__ void kB(const float* __restrict__ adj,
                   const float* __restrict__ lnw,
                   const float* __restrict__ lnb,
                   const float* __restrict__ Wh,
                   const float* __restrict__ ah) {
    int tid = threadIdx.x;
    int w = tid >> 5, lane = tid & 31;

    for (int rr = 0; rr < 32; rr++) {
        int i = w*32 + rr;
        int cnt = 0;
        #pragma unroll
        for (int cc = 0; cc < 8; cc++) {
            float av = adj[i*Nn + cc*32 + lane];
            unsigned m = __ballot_sync(0xffffffffu, av > 0.0f);
            if (av > 0.0f) {
                int pos = cnt + __popc(m & ((1u << lane) - 1u));
                if (pos < DMAX) g_nbr[i*DMAX + pos] = cc*32 + lane;
            }
            cnt += __popc(m);
        }
        if (lane == 0) g_deg[i] = (cnt > DMAX) ? DMAX : cnt;
    }

    // v vectors: 1024 entries, 4 per thread
    #pragma unroll
    for (int r = 0; r < 4; r++) {
        int id = tid + r*256;
        int h = id >> 7, half = (id >> 6) & 1, c = id & 63;
        const float* wr = Wh + (h*64 + c)*64;
        const float* ar = ah + h*128 + half*64;
        float s = 0.0f;
        #pragma unroll
        for (int d2 = 0; d2 < 64; d2++) s = fmaf(wr[d2], ar[d2], s);
        g_v[id] = s;
    }

    for (int idx = tid; idx < C2c*Nn; idx += 256) {
        int c = idx >> 8, n2 = idx & 255;
        g_lnwT[idx] = lnw[n2*C2c + c];
        g_lnbT[idx] = lnb[n2*C2c + c];
    }
}

// ---------------------------------------------------------------------------
// Kernel Agg: all-8-head GAT + residual, writes x_s directly.
// grid (4, TP, B) = 320 blocks, 256 threads. Warp-per-row, 8 rows/warp.
// No cross-lane communication: softmax without max-subtraction, per-lane
// redundant sums, fused 8-head gather (1 LDS.64 feeds 16 FMA).
// ---------------------------------------------------------------------------
__global__ void kAgg() {
    extern __shared__ float sm[];
    float* sxg   = sm;                 // 256*66 = 16896
    float* se2   = sxg + 16896;        // 8*256 = 2048
    float* se1   = se2 + 2048;         // 8*64  = 512 (own rows)
    float* sv    = se1 + 512;          // 16*64 = 1024
    float* stash = sv + 1024;          // 8 warps * 864 (768 p + 96 nbr)
    int tid = threadIdx.x;
    int q = blockIdx.x, t = blockIdx.y, b = blockIdx.z;
    int base = ((b*TP + t)*Nn)*C1c;
    int i0 = q*64;

    for (int idx = tid; idx < Nn*C1c/4; idx += 256) {
        float4 v = ((const float4*)(g_xg + base))[idx];
        int n2 = idx >> 4, cq = (idx & 15) * 4;
        float* p = sxg + n2*66 + cq;
        p[0] = v.x; p[1] = v.y; p[2] = v.z; p[3] = v.w;
    }
    for (int idx = tid; idx < 1024; idx += 256) sv[idx] = g_v[idx];
    __syncthreads();

    {   // e2 for all n, e1 for own 64 rows
        int n = tid;
        float a2[8], a1[8];
        #pragma unroll
        for (int h = 0; h < 8; h++) { a2[h] = 0.0f; a1[h] = 0.0f; }
        for (int c = 0; c < 64; c++) {
            float xv = sxg[n*66 + c];
            #pragma unroll
            for (int h = 0; h < 8; h++) {
                a1[h] = fmaf(xv, sv[(h*2)*64 + c],     a1[h]);
                a2[h] = fmaf(xv, sv[(h*2 + 1)*64 + c], a2[h]);
            }
        }
        #pragma unroll
        for (int h = 0; h < 8; h++) se2[h*256 + n] = a2[h];
        if (n >= i0 && n < i0 + 64) {
            #pragma unroll
            for (int h = 0; h < 8; h++) se1[h*64 + (n - i0)] = a1[h];
        }
    }
    __syncthreads();

    int w = tid >> 5, lane = tid & 31;
    float* sp  = stash + w*864;
    int*   snb = (int*)(sp + 768);
    int c0 = 2*lane;

    for (int rr = 0; rr < 8; rr++) {
        int il = w*8 + rr;
        int i = i0 + il;
        int d = g_deg[i];
        for (int k = lane; k < d; k += 32) snb[k] = g_nbr[i*DMAX + k];
        __syncwarp();

        float e1v[8];
        #pragma unroll
        for (int h = 0; h < 8; h++) e1v[h] = se1[h*64 + il];

        // stage A: unnormalized attention weights p[k][h]
        #pragma unroll
        for (int kk = 0; kk < 3; kk++) {
            int k = lane + kk*32;
            if (k < d) {
                int j = snb[k];
                float4 pa, pb;
                {
                    float s0 = e1v[0] + se2[0*256 + j];
                    float s1 = e1v[1] + se2[1*256 + j];
                    float s2 = e1v[2] + se2[2*256 + j];
                    float s3 = e1v[3] + se2[3*256 + j];
                    pa.x = __expf(fmaxf(s0, ALPHA*s0));
                    pa.y = __expf(fmaxf(s1, ALPHA*s1));
                    pa.z = __expf(fmaxf(s2, ALPHA*s2));
                    pa.w = __expf(fmaxf(s3, ALPHA*s3));
                }
                {
                    float s4 = e1v[4] + se2[4*256 + j];
                    float s5 = e1v[5] + se2[5*256 + j];
                    float s6 = e1v[6] + se2[6*256 + j];
                    float s7 = e1v[7] + se2[7*256 + j];
                    pb.x = __expf(fmaxf(s4, ALPHA*s4));
                    pb.y = __expf(fmaxf(s5, ALPHA*s5));
                    pb.z = __expf(fmaxf(s6, ALPHA*s6));
                    pb.w = __expf(fmaxf(s7, ALPHA*s7));
                }
                *(float4*)&sp[k*8]     = pa;
                *(float4*)&sp[k*8 + 4] = pb;
            }
        }
        __syncwarp();

        // stage B: fused 8-head gather-aggregate + per-lane redundant sums
        float a[16];
        float S[8];
        #pragma unroll
        for (int u = 0; u < 16; u++) a[u] = 0.0f;
        #pragma unroll
        for (int h = 0; h < 8; h++) S[h] = 0.0f;

        int j = (d > 0) ? snb[0] : 0;
        for (int k = 0; k < d; k++) {
            int jn = (k + 1 < d) ? snb[k + 1] : 0;
            float4 pa = *(const float4*)&sp[k*8];
            float4 pb = *(const float4*)&sp[k*8 + 4];
            float2 xv = *(const float2*)&sxg[j*66 + c0];
            a[0]  = fmaf(pa.x, xv.x, a[0]);   a[1]  = fmaf(pa.x, xv.y, a[1]);
            a[2]  = fmaf(pa.y, xv.x, a[2]);   a[3]  = fmaf(pa.y, xv.y, a[3]);
            a[4]  = fmaf(pa.z, xv.x, a[4]);   a[5]  = fmaf(pa.z, xv.y, a[5]);
            a[6]  = fmaf(pa.w, xv.x, a[6]);   a[7]  = fmaf(pa.w, xv.y, a[7]);
            a[8]  = fmaf(pb.x, xv.x, a[8]);   a[9]  = fmaf(pb.x, xv.y, a[9]);
            a[10] = fmaf(pb.y, xv.x, a[10]);  a[11] = fmaf(pb.y, xv.y, a[11]);
            a[12] = fmaf(pb.z, xv.x, a[12]);  a[13] = fmaf(pb.z, xv.y, a[13]);
            a[14] = fmaf(pb.w, xv.x, a[14]);  a[15] = fmaf(pb.w, xv.y, a[15]);
            S[0] += pa.x; S[1] += pa.y; S[2] += pa.z; S[3] += pa.w;
            S[4] += pb.x; S[5] += pb.y; S[6] += pb.z; S[7] += pb.w;
            j = jn;
        }

        float rx = 0.0f, ry = 0.0f;
        #pragma unroll
        for (int h = 0; h < 8; h++) {
            float rs = 1.0f / S[h];
            rx += tanh_ap(a[2*h]     * rs);
            ry += tanh_ap(a[2*h + 1] * rs);
        }
        float2 x0 = *(const float2*)&sxg[i*66 + c0];
        float2 o;
        o.x = x0.x + rx * 0.125f;
        o.y = x0.y + ry * 0.125f;
        *(float2*)&g_xs[base + i*64 + c0] = o;
        __syncwarp();   // sp/snb reused next row
    }
}

// ---------------------------------------------------------------------------
// Kernel D1: conv2 + residual + relu + partial LN stats.
// grid (T2, B, 4 cout-chunks) = 256 blocks, 256 threads (n).
// ---------------------------------------------------------------------------
__global__ void kD1(const float* __restrict__ w2, const float* __restrict__ b2) {
    extern __shared__ float sm[];
    float* sx2 = sm;            // 3*256*17 = 13056
    float* sw2 = sm + 13056;    // 48*16 = 768
    __shared__ float red[16];
    int tid = threadIdx.x;
    int t2 = blockIdx.x, b = blockIdx.y, cs = blockIdx.z;
    int n = tid;

    float acc[16];
    #pragma unroll
    for (int cc = 0; cc < 16; cc++) acc[cc] = __ldg(b2 + cs*16 + cc);

    #pragma unroll
    for (int g = 0; g < 4; g++) {
        __syncthreads();
        for (int idx = tid; idx < 16*3*256; idx += 256) {
            int ci = idx & 15;
            int nn = (idx >> 4) & 255;
            int kt = idx >> 12;
            sx2[(kt*256 + nn)*17 + ci] =
                g_xs[((b*TP + t2 + kt)*Nn + nn)*C1c + g*16 + ci];
        }
        for (int idx = tid; idx < 48*16; idx += 256) {
            int cout = idx & 15;
            int ck = idx >> 4;               // ci*3 + kt
            int ci = ck / 3, kt = ck % 3;
            sw2[ck*16 + cout] = w2[(cs*16 + cout)*(C1c*KTc) + (g*16 + ci)*KTc + kt];
        }
        __syncthreads();

        for (int ci = 0; ci < 16; ci++) {
            #pragma unroll
            for (int kt = 0; kt < 3; kt++) {
                float xv = sx2[(kt*256 + n)*17 + ci];
                const float4* wr = (const float4*)(sw2 + (ci*3 + kt)*16);
                #pragma unroll
                for (int qq = 0; qq < 4; qq++) {
                    float4 wv = wr[qq];
                    acc[qq*4+0] = fmaf(xv, wv.x, acc[qq*4+0]);
                    acc[qq*4+1] = fmaf(xv, wv.y, acc[qq*4+1]);
                    acc[qq*4+2] = fmaf(xv, wv.z, acc[qq*4+2]);
                    acc[qq*4+3] = fmaf(xv, wv.w, acc[qq*4+3]);
                }
            }
        }
        if (g == cs) {
            #pragma unroll
            for (int cc = 0; cc < 16; cc++)
                acc[cc] += sx2[(2*256 + n)*17 + cc];
        }
    }

    float ls = 0.0f, lss = 0.0f;
    #pragma unroll
    for (int cc = 0; cc < 16; cc++) {
        float v = fmaxf(acc[cc], 0.0f);
        acc[cc] = v;
        ls += v;
        lss = fmaf(v, v, lss);
    }
    #pragma unroll
    for (int o = 16; o > 0; o >>= 1) {
        ls  += __shfl_xor_sync(0xffffffffu, ls,  o);
        lss += __shfl_xor_sync(0xffffffffu, lss, o);
    }
    int w = tid >> 5, lane = tid & 31;
    if (lane == 0) { red[w] = ls; red[w + 8] = lss; }
    __syncthreads();
    if (tid == 0) {
        float S = 0.0f, SS = 0.0f;
        #pragma unroll
        for (int i = 0; i < 8; i++) { S += red[i]; SS += red[i + 8]; }
        int bt = b*T2 + t2;
        g_psum[(bt*4 + cs)*2]     = S;
        g_psum[(bt*4 + cs)*2 + 1] = SS;
    }

    int ybase = ((b*T2 + t2)*C2c + cs*16)*Nn;
    #pragma unroll
    for (int cc = 0; cc < 16; cc++)
        g_y[ybase + cc*Nn + n] = acc[cc];
}

// ---------------------------------------------------------------------------
// Kernel E: LayerNorm + transposed store. grid (T2, B, 4), 256 threads.
// ---------------------------------------------------------------------------
__global__ void kE(float* __restrict__ out) {
    int t2 = blockIdx.x, b = blockIdx.y, cs = blockIdx.z;
    int bt = b*T2 + t2;
    float S = 0.0f, SS = 0.0f;
    #pragma unroll
    for (int qq = 0; qq < 4; qq++) {
        S  += g_psum[(bt*4 + qq)*2];
        SS += g_psum[(bt*4 + qq)*2 + 1];
    }
    float mu   = S * (1.0f/16384.0f);
    float var  = SS * (1.0f/16384.0f) - mu*mu;
    float rstd = rsqrtf(var + 1e-5f);
    int n = threadIdx.x;
    #pragma unroll
    for (int cc = 0; cc < 16; cc++) {
        int c = cs*16 + cc;
        float yv = (g_y[(bt*C2c + c)*Nn + n] - mu) * rstd;
        out[((b*C2c + c)*T2 + t2)*Nn + n] =
            fmaf(yv, g_lnwT[c*Nn + n], g_lnbT[c*Nn + n]);
    }
}

// ---------------------------------------------------------------------------
extern "C" void kernel_launch(void* const* d_in, const int* in_sizes, int n_in,
                              void* d_out, int out_size) {
    const float* x   = (const float*)d_in[0];
    const float* adj = (const float*)d_in[1];
    const float* w1  = (const float*)d_in[2];
    const float* b1  = (const float*)d_in[3];
    const float* w2  = (const float*)d_in[4];
    const float* b2  = (const float*)d_in[5];
    const float* Wh  = (const float*)d_in[6];
    const float* ah  = (const float*)d_in[7];
    const float* lnw = (const float*)d_in[8];
    const float* lnb = (const float*)d_in[9];
    float* out = (float*)d_out;

    const int smA   = (6144 + 3072*4) * 4;                       // 36864... sx 6144 + swp 3072 floats
    const int smAgg = (16896 + 2048 + 512 + 1024 + 8*864) * 4;   // 109568
    const int smD   = (13056 + 768) * 4;                         // 55296
    cudaFuncSetAttribute(kA,   cudaFuncAttributeMaxDynamicSharedMemorySize, smA);
    cudaFuncSetAttribute(kAgg, cudaFuncAttributeMaxDynamicSharedMemorySize, smAgg);
    cudaFuncSetAttribute(kD1,  cudaFuncAttributeMaxDynamicSharedMemorySize, smD);

    kA<<<dim3(4, TP, Bn), 128, smA>>>(x, w1, b1);
    kB<<<1, 256>>>(adj, lnw, lnb, Wh, ah);
    kAgg<<<dim3(4, TP, Bn), 256, smAgg>>>();
    kD1<<<dim3(T2, Bn, 4), 256, smD>>>(w2, b2);
    kE<<<dim3(T2, Bn, 4), 256>>>(out);
}

// round 6
// speedup vs baseline: 2.9044x; 1.5258x over previous
#include <cuda_runtime.h>
#include <math.h>

#define Bn 8
#define C0 16
#define C1c 64
#define C2c 64
#define Tt 12
#define TP 10
#define T2 8
#define Nn 256
#define KTc 3
#define Hh 8
#define ALPHA 0.2f
#define DMAX 96
#define XSZ (Bn*TP*Nn*C1c)   // 1310720

// scratch (static device allocations — allowed)
__device__ float g_xg[XSZ];          // x_t1 in [b,t,n,c]
__device__ float g_xs[XSZ];          // x_t1 + gat -> x_s
__device__ float g_y[Bn*T2*C2c*Nn];  // conv2+relu output, [bt][c][n]
__device__ float g_psum[Bn*T2*4*2];  // per (bt, cs) partial LN sums
__device__ int   g_deg[Nn];
__device__ int   g_nbr[Nn*DMAX];
__device__ float g_vT[64*16];        // vT[c*16 + h*2+half]
__device__ float g_lnwT[C2c*Nn];
__device__ float g_lnbT[C2c*Nn];

__device__ __forceinline__ float tanh_ap(float x) {
    float y;
    asm("tanh.approx.f32 %0, %1;" : "=f"(y) : "f"(x));
    return y;
}

// ---------------------------------------------------------------------------
// Kernel A: conv1 (KT=3) + GLU. grid (8, TP, B): octant = (n-half, c-eighth).
// 128 threads, 16 couts per block.
// ---------------------------------------------------------------------------
__global__ void kA(const float* __restrict__ x,
                   const float* __restrict__ w1,
                   const float* __restrict__ b1) {
    extern __shared__ float sm[];
    float*  sx  = sm;                       // 48*128 = 6144 (reused as sxt 16*129)
    float4* swp = (float4*)(sm + 6144);     // 16*24 float4 = 1536 floats
    int tid = threadIdx.x;
    int q = blockIdx.x, t = blockIdx.y, b = blockIdx.z;
    int nh = q & 1, ch = q >> 1;            // ch: 0..3 -> 16 couts
    int n0 = nh * 128;

    #pragma unroll
    for (int u = 0; u < 48; u++) {
        sx[u*128 + tid] = x[((b*C0 + u/3)*Tt + t + (u%3))*Nn + n0 + tid];
    }
    for (int idx = tid; idx < 16*24; idx += 128) {
        int cl = idx / 24, k2 = idx % 24;
        int c = ch*16 + cl;
        float4 v;
        v.x = w1[c*48 + 2*k2];
        v.y = w1[c*48 + 2*k2 + 1];
        v.z = w1[(c+64)*48 + 2*k2];
        v.w = w1[(c+64)*48 + 2*k2 + 1];
        swp[idx] = v;
    }
    __syncthreads();

    int nl = tid;
    float xr[48];
    #pragma unroll
    for (int k = 0; k < 48; k++) xr[k] = sx[k*128 + nl];
    __syncthreads();   // sx reused as sxt below

    #pragma unroll
    for (int cl = 0; cl < 16; cl++) {
        int c = ch*16 + cl;
        float am = __ldg(b1 + c);
        float ag = __ldg(b1 + c + 64);
        #pragma unroll
        for (int k2 = 0; k2 < 24; k2++) {
            float4 w = swp[cl*24 + k2];
            am = fmaf(xr[2*k2],   w.x, am);
            am = fmaf(xr[2*k2+1], w.y, am);
            ag = fmaf(xr[2*k2],   w.z, ag);
            ag = fmaf(xr[2*k2+1], w.w, ag);
        }
        float xin = (c < C0) ? xr[c*3 + 2] : 0.0f;
        float val = (am + xin) * (1.0f / (1.0f + __expf(-ag)));
        sx[cl*129 + nl] = val;
    }
    __syncthreads();

    int base = ((b*TP + t)*Nn + n0)*C1c + ch*16;
    for (int idx = tid; idx < 128*16; idx += 128) {
        int n2 = idx >> 4, cl = idx & 15;
        g_xg[base + n2*64 + cl] = sx[cl*129 + n2];
    }
}

// ---------------------------------------------------------------------------
// Kernel B: grid 41 blocks x 256 threads.
//  blocks 0..31 : adjacency ballot-compaction, warp-per-row (8 rows/block)
//  blocks 32..39: transposed LayerNorm params
//  block  40    : v vectors (transposed layout)
// ---------------------------------------------------------------------------
__global__ void kB(const float* __restrict__ adj,
                   const float* __restrict__ lnw,
                   const float* __restrict__ lnb,
                   const float* __restrict__ Wh,
                   const float* __restrict__ ah) {
    int tid = threadIdx.x;
    int bid = blockIdx.x;

    if (bid < 32) {
        int w = tid >> 5, lane = tid & 31;
        int i = bid*8 + w;
        int cnt = 0;
        #pragma unroll
        for (int cc = 0; cc < 8; cc++) {
            float av = adj[i*Nn + cc*32 + lane];
            unsigned m = __ballot_sync(0xffffffffu, av > 0.0f);
            if (av > 0.0f) {
                int pos = cnt + __popc(m & ((1u << lane) - 1u));
                if (pos < DMAX) g_nbr[i*DMAX + pos] = cc*32 + lane;
            }
            cnt += __popc(m);
        }
        if (lane == 0) g_deg[i] = (cnt > DMAX) ? DMAX : cnt;
    } else if (bid < 40) {
        int p = bid - 32;
        #pragma unroll
        for (int k = 0; k < 8; k++) {
            int idx = p*2048 + k*256 + tid;
            int c = idx >> 8, n2 = idx & 255;
            g_lnwT[idx] = lnw[n2*C2c + c];
            g_lnbT[idx] = lnb[n2*C2c + c];
        }
    } else {
        #pragma unroll
        for (int r = 0; r < 4; r++) {
            int id = tid + r*256;
            int j = id & 15, c = id >> 4;     // j = h*2 + half
            int h = j >> 1, half = j & 1;
            const float* wr = Wh + (h*64 + c)*64;
            const float* ar = ah + h*128 + half*64;
            float s = 0.0f;
            #pragma unroll
            for (int d2 = 0; d2 < 64; d2++) s = fmaf(wr[d2], ar[d2], s);
            g_vT[c*16 + j] = s;
        }
    }
}

// ---------------------------------------------------------------------------
// Kernel Agg: all-8-head GAT + residual -> x_s. grid (4, TP, B), 256 threads.
// Warp-per-row, 8 rows/warp. No cross-lane communication.
// ---------------------------------------------------------------------------
__global__ void kAgg() {
    extern __shared__ float sm[];
    float* sxg   = sm;                 // 256*66 = 16896
    float* se2   = sxg + 16896;        // 8*256 = 2048
    float* se1   = se2 + 2048;         // 8*64  = 512 (own rows)
    float* svT   = se1 + 512;          // 64*16 = 1024
    float* stash = svT + 1024;         // 8 warps * 864 (768 p + 96 nbr)
    int tid = threadIdx.x;
    int q = blockIdx.x, t = blockIdx.y, b = blockIdx.z;
    int base = ((b*TP + t)*Nn)*C1c;
    int i0 = q*64;

    for (int idx = tid; idx < Nn*C1c/4; idx += 256) {
        float4 v = ((const float4*)(g_xg + base))[idx];
        int n2 = idx >> 4, cq = (idx & 15) * 4;
        float* p = sxg + n2*66 + cq;
        p[0] = v.x; p[1] = v.y; p[2] = v.z; p[3] = v.w;
    }
    for (int idx = tid; idx < 1024; idx += 256) svT[idx] = g_vT[idx];
    __syncthreads();

    {   // e2 for all n, e1 for own 64 rows; vT[c][16] -> 4x LDS128 broadcast
        int n = tid;
        float a1[8], a2[8];
        #pragma unroll
        for (int h = 0; h < 8; h++) { a1[h] = 0.0f; a2[h] = 0.0f; }
        #pragma unroll 8
        for (int c = 0; c < 64; c++) {
            float xv = sxg[n*66 + c];
            const float4* vq = (const float4*)(svT + c*16);
            float4 q0 = vq[0], q1 = vq[1], q2 = vq[2], q3 = vq[3];
            a1[0] = fmaf(xv, q0.x, a1[0]); a2[0] = fmaf(xv, q0.y, a2[0]);
            a1[1] = fmaf(xv, q0.z, a1[1]); a2[1] = fmaf(xv, q0.w, a2[1]);
            a1[2] = fmaf(xv, q1.x, a1[2]); a2[2] = fmaf(xv, q1.y, a2[2]);
            a1[3] = fmaf(xv, q1.z, a1[3]); a2[3] = fmaf(xv, q1.w, a2[3]);
            a1[4] = fmaf(xv, q2.x, a1[4]); a2[4] = fmaf(xv, q2.y, a2[4]);
            a1[5] = fmaf(xv, q2.z, a1[5]); a2[5] = fmaf(xv, q2.w, a2[5]);
            a1[6] = fmaf(xv, q3.x, a1[6]); a2[6] = fmaf(xv, q3.y, a2[6]);
            a1[7] = fmaf(xv, q3.z, a1[7]); a2[7] = fmaf(xv, q3.w, a2[7]);
        }
        #pragma unroll
        for (int h = 0; h < 8; h++) se2[h*256 + n] = a2[h];
        if (n >= i0 && n < i0 + 64) {
            #pragma unroll
            for (int h = 0; h < 8; h++) se1[h*64 + (n - i0)] = a1[h];
        }
    }
    __syncthreads();

    int w = tid >> 5, lane = tid & 31;
    float* sp  = stash + w*864;
    int*   snb = (int*)(sp + 768);
    int c0 = 2*lane;

    for (int rr = 0; rr < 8; rr++) {
        int il = w*8 + rr;
        int i = i0 + il;
        int d = g_deg[i];
        for (int k = lane; k < d; k += 32) snb[k] = g_nbr[i*DMAX + k];
        __syncwarp();

        float e1v[8];
        #pragma unroll
        for (int h = 0; h < 8; h++) e1v[h] = se1[h*64 + il];

        // stage A: unnormalized attention weights p[k][h]
        #pragma unroll
        for (int kk = 0; kk < 3; kk++) {
            int k = lane + kk*32;
            if (k < d) {
                int j = snb[k];
                float4 pa, pb;
                {
                    float s0 = e1v[0] + se2[0*256 + j];
                    float s1 = e1v[1] + se2[1*256 + j];
                    float s2 = e1v[2] + se2[2*256 + j];
                    float s3 = e1v[3] + se2[3*256 + j];
                    pa.x = __expf(fmaxf(s0, ALPHA*s0));
                    pa.y = __expf(fmaxf(s1, ALPHA*s1));
                    pa.z = __expf(fmaxf(s2, ALPHA*s2));
                    pa.w = __expf(fmaxf(s3, ALPHA*s3));
                }
                {
                    float s4 = e1v[4] + se2[4*256 + j];
                    float s5 = e1v[5] + se2[5*256 + j];
                    float s6 = e1v[6] + se2[6*256 + j];
                    float s7 = e1v[7] + se2[7*256 + j];
                    pb.x = __expf(fmaxf(s4, ALPHA*s4));
                    pb.y = __expf(fmaxf(s5, ALPHA*s5));
                    pb.z = __expf(fmaxf(s6, ALPHA*s6));
                    pb.w = __expf(fmaxf(s7, ALPHA*s7));
                }
                *(float4*)&sp[k*8]     = pa;
                *(float4*)&sp[k*8 + 4] = pb;
            }
        }
        __syncwarp();

        // stage B: fused 8-head gather-aggregate + per-lane redundant sums
        float a[16];
        float S[8];
        #pragma unroll
        for (int u = 0; u < 16; u++) a[u] = 0.0f;
        #pragma unroll
        for (int h = 0; h < 8; h++) S[h] = 0.0f;

        int j = (d > 0) ? snb[0] : 0;
        for (int k = 0; k < d; k++) {
            int jn = (k + 1 < d) ? snb[k + 1] : 0;
            float4 pa = *(const float4*)&sp[k*8];
            float4 pb = *(const float4*)&sp[k*8 + 4];
            float2 xv = *(const float2*)&sxg[j*66 + c0];
            a[0]  = fmaf(pa.x, xv.x, a[0]);   a[1]  = fmaf(pa.x, xv.y, a[1]);
            a[2]  = fmaf(pa.y, xv.x, a[2]);   a[3]  = fmaf(pa.y, xv.y, a[3]);
            a[4]  = fmaf(pa.z, xv.x, a[4]);   a[5]  = fmaf(pa.z, xv.y, a[5]);
            a[6]  = fmaf(pa.w, xv.x, a[6]);   a[7]  = fmaf(pa.w, xv.y, a[7]);
            a[8]  = fmaf(pb.x, xv.x, a[8]);   a[9]  = fmaf(pb.x, xv.y, a[9]);
            a[10] = fmaf(pb.y, xv.x, a[10]);  a[11] = fmaf(pb.y, xv.y, a[11]);
            a[12] = fmaf(pb.z, xv.x, a[12]);  a[13] = fmaf(pb.z, xv.y, a[13]);
            a[14] = fmaf(pb.w, xv.x, a[14]);  a[15] = fmaf(pb.w, xv.y, a[15]);
            S[0] += pa.x; S[1] += pa.y; S[2] += pa.z; S[3] += pa.w;
            S[4] += pb.x; S[5] += pb.y; S[6] += pb.z; S[7] += pb.w;
            j = jn;
        }

        float rx = 0.0f, ry = 0.0f;
        #pragma unroll
        for (int h = 0; h < 8; h++) {
            float rs = 1.0f / S[h];
            rx += tanh_ap(a[2*h]     * rs);
            ry += tanh_ap(a[2*h + 1] * rs);
        }
        float2 x0 = *(const float2*)&sxg[i*66 + c0];
        float2 o;
        o.x = x0.x + rx * 0.125f;
        o.y = x0.y + ry * 0.125f;
        *(float2*)&g_xs[base + i*64 + c0] = o;
        __syncwarp();   // sp/snb reused next row
    }
}

// ---------------------------------------------------------------------------
// Kernel D1: conv2 + residual + relu + partial LN stats.
// grid (T2, B, 4 cout-chunks), 512 threads: half = tid>>8 (8 couts), n = tid&255.
// ---------------------------------------------------------------------------
__global__ void kD1(const float* __restrict__ w2, const float* __restrict__ b2) {
    extern __shared__ float sm[];
    float* sx2  = sm;            // 3*256*17 = 13056
    float* sw2a = sm + 13056;    // 4*48*16 = 3072
    __shared__ float red[32];
    int tid = threadIdx.x;
    int t2 = blockIdx.x, b = blockIdx.y, cs = blockIdx.z;
    int half = tid >> 8, n = tid & 255;
    int bT = b*TP + t2;

    // weights for all 4 g-chunks, layout [g][ci*3+kt][16]
    // idx = (g*48 + ck)*16 + cout  (per-g block = 768 entries)
    for (int idx = tid; idx < 4*48*16; idx += 512) {
        int cout = idx & 15;
        int r = idx >> 4;        // 0..191
        int g = r / 48;
        int ck = r % 48;
        int ci = ck / 3, kt = ck % 3;
        sw2a[idx] = w2[(cs*16 + cout)*(C1c*KTc) + (g*16 + ci)*KTc + kt];
    }

    float acc[8];
    #pragma unroll
    for (int cc = 0; cc < 8; cc++) acc[cc] = __ldg(b2 + cs*16 + half*8 + cc);

    int ci_s = tid & 15, nb0 = tid >> 4;     // staging coords (512 threads)

    #pragma unroll
    for (int g = 0; g < 4; g++) {
        __syncthreads();
        #pragma unroll
        for (int u = 0; u < 24; u++) {
            int linear = nb0 + 32*u;          // 0..767
            int kt = linear >> 8, nn = linear & 255;
            sx2[(kt*256 + nn)*17 + ci_s] =
                g_xs[((bT + kt)*Nn + nn)*C1c + g*16 + ci_s];
        }
        __syncthreads();

        #pragma unroll 4
        for (int ci = 0; ci < 16; ci++) {
            #pragma unroll
            for (int kt = 0; kt < 3; kt++) {
                float xv = sx2[(kt*256 + n)*17 + ci];
                const float4* wr = (const float4*)(sw2a + (g*48 + ci*3 + kt)*16 + half*8);
                float4 w0 = wr[0], w1v = wr[1];
                acc[0] = fmaf(xv, w0.x,  acc[0]);
                acc[1] = fmaf(xv, w0.y,  acc[1]);
                acc[2] = fmaf(xv, w0.z,  acc[2]);
                acc[3] = fmaf(xv, w0.w,  acc[3]);
                acc[4] = fmaf(xv, w1v.x, acc[4]);
                acc[5] = fmaf(xv, w1v.y, acc[5]);
                acc[6] = fmaf(xv, w1v.z, acc[6]);
                acc[7] = fmaf(xv, w1v.w, acc[7]);
            }
        }
        if (g == cs) {
            #pragma unroll
            for (int cc = 0; cc < 8; cc++)
                acc[cc] += sx2[(2*256 + n)*17 + half*8 + cc];
        }
    }

    float ls = 0.0f, lss = 0.0f;
    #pragma unroll
    for (int cc = 0; cc < 8; cc++) {
        float v = fmaxf(acc[cc], 0.0f);
        acc[cc] = v;
        ls += v;
        lss = fmaf(v, v, lss);
    }
    #pragma unroll
    for (int o = 16; o > 0; o >>= 1) {
        ls  += __shfl_xor_sync(0xffffffffu, ls,  o);
        lss += __shfl_xor_sync(0xffffffffu, lss, o);
    }
    int w = tid >> 5, lane = tid & 31;
    if (lane == 0) { red[w] = ls; red[w + 16] = lss; }
    __syncthreads();
    if (tid == 0) {
        float S = 0.0f, SS = 0.0f;
        #pragma unroll
        for (int i = 0; i < 16; i++) { S += red[i]; SS += red[i + 16]; }
        int bt = b*T2 + t2;
        g_psum[(bt*4 + cs)*2]     = S;
        g_psum[(bt*4 + cs)*2 + 1] = SS;
    }

    int ybase = ((b*T2 + t2)*C2c + cs*16 + half*8)*Nn;
    #pragma unroll
    for (int cc = 0; cc < 8; cc++)
        g_y[ybase + cc*Nn + n] = acc[cc];
}

// ---------------------------------------------------------------------------
// Kernel E: LayerNorm + transposed store. grid (T2, B, 4), 256 threads.
// ---------------------------------------------------------------------------
__global__ void kE(float* __restrict__ out) {
    int t2 = blockIdx.x, b = blockIdx.y, cs = blockIdx.z;
    int bt = b*T2 + t2;
    float S = 0.0f, SS = 0.0f;
    #pragma unroll
    for (int qq = 0; qq < 4; qq++) {
        S  += g_psum[(bt*4 + qq)*2];
        SS += g_psum[(bt*4 + qq)*2 + 1];
    }
    float mu   = S * (1.0f/16384.0f);
    float var  = SS * (1.0f/16384.0f) - mu*mu;
    float rstd = rsqrtf(var + 1e-5f);
    int n = threadIdx.x;
    #pragma unroll
    for (int cc = 0; cc < 16; cc++) {
        int c = cs*16 + cc;
        float yv = (g_y[(bt*C2c + c)*Nn + n] - mu) * rstd;
        out[((b*C2c + c)*T2 + t2)*Nn + n] =
            fmaf(yv, g_lnwT[c*Nn + n], g_lnbT[c*Nn + n]);
    }
}

// ---------------------------------------------------------------------------
extern "C" void kernel_launch(void* const* d_in, const int* in_sizes, int n_in,
                              void* d_out, int out_size) {
    const float* x   = (const float*)d_in[0];
    const float* adj = (const float*)d_in[1];
    const float* w1  = (const float*)d_in[2];
    const float* b1  = (const float*)d_in[3];
    const float* w2  = (const float*)d_in[4];
    const float* b2  = (const float*)d_in[5];
    const float* Wh  = (const float*)d_in[6];
    const float* ah  = (const float*)d_in[7];
    const float* lnw = (const float*)d_in[8];
    const float* lnb = (const float*)d_in[9];
    float* out = (float*)d_out;

    const int smA   = (6144 + 1536) * 4;                         // 30720
    const int smAgg = (16896 + 2048 + 512 + 1024 + 8*864) * 4;   // 109568
    const int smD   = (13056 + 3072) * 4;                        // 64512
    cudaFuncSetAttribute(kA,   cudaFuncAttributeMaxDynamicSharedMemorySize, smA);
    cudaFuncSetAttribute(kAgg, cudaFuncAttributeMaxDynamicSharedMemorySize, smAgg);
    cudaFuncSetAttribute(kD1,  cudaFuncAttributeMaxDynamicSharedMemorySize, smD);

    kA<<<dim3(8, TP, Bn), 128, smA>>>(x, w1, b1);
    kB<<<41, 256>>>(adj, lnw, lnb, Wh, ah);
    kAgg<<<dim3(4, TP, Bn), 256, smAgg>>>();
    kD1<<<dim3(T2, Bn, 4), 512, smD>>>(w2, b2);
    kE<<<dim3(T2, Bn, 4), 256>>>(out);
}

// round 7
// speedup vs baseline: 2.9534x; 1.0168x over previous
#include <cuda_runtime.h>
#include <math.h>

#define Bn 8
#define C0 16
#define C1c 64
#define C2c 64
#define Tt 12
#define TP 10
#define T2 8
#define Nn 256
#define KTc 3
#define Hh 8
#define ALPHA 0.2f
#define DMAX 96
#define XSZ (Bn*TP*Nn*C1c)   // 1310720

// scratch (static device allocations — allowed)
__device__ float g_xg[XSZ];          // x_t1 in [b,t,n,c]
__device__ float g_xs[XSZ];          // x_t1 + gat -> x_s
__device__ float g_y[Bn*T2*C2c*Nn];  // conv2+relu output, [bt][c][n]
__device__ float g_psum[Bn*T2*4*2];  // per (bt, cs) partial LN sums
__device__ int   g_deg[Nn];
__device__ int   g_nbr[Nn*DMAX];
__device__ float g_vT[64*16];        // vT[c*16 + h*2+half]
__device__ float g_lnwT[C2c*Nn];
__device__ float g_lnbT[C2c*Nn];

__device__ __forceinline__ float tanh_ap(float x) {
    float y;
    asm("tanh.approx.f32 %0, %1;" : "=f"(y) : "f"(x));
    return y;
}

// ---------------------------------------------------------------------------
// Kernel A: conv1 (KT=3) + GLU. grid (8, TP, B): octant = (n-half, c-eighth).
// 128 threads, 16 couts per block.
// ---------------------------------------------------------------------------
__global__ void kA(const float* __restrict__ x,
                   const float* __restrict__ w1,
                   const float* __restrict__ b1) {
    extern __shared__ float sm[];
    float*  sx  = sm;                       // 48*128 = 6144 (reused as sxt 16*129)
    float4* swp = (float4*)(sm + 6144);     // 16*24 float4 = 1536 floats
    int tid = threadIdx.x;
    int q = blockIdx.x, t = blockIdx.y, b = blockIdx.z;
    int nh = q & 1, ch = q >> 1;            // ch: 0..3 -> 16 couts
    int n0 = nh * 128;

    #pragma unroll
    for (int u = 0; u < 48; u++) {
        sx[u*128 + tid] = x[((b*C0 + u/3)*Tt + t + (u%3))*Nn + n0 + tid];
    }
    for (int idx = tid; idx < 16*24; idx += 128) {
        int cl = idx / 24, k2 = idx % 24;
        int c = ch*16 + cl;
        float4 v;
        v.x = w1[c*48 + 2*k2];
        v.y = w1[c*48 + 2*k2 + 1];
        v.z = w1[(c+64)*48 + 2*k2];
        v.w = w1[(c+64)*48 + 2*k2 + 1];
        swp[idx] = v;
    }
    __syncthreads();

    int nl = tid;
    float xr[48];
    #pragma unroll
    for (int k = 0; k < 48; k++) xr[k] = sx[k*128 + nl];
    __syncthreads();   // sx reused as sxt below

    #pragma unroll
    for (int cl = 0; cl < 16; cl++) {
        int c = ch*16 + cl;
        float am = __ldg(b1 + c);
        float ag = __ldg(b1 + c + 64);
        #pragma unroll
        for (int k2 = 0; k2 < 24; k2++) {
            float4 w = swp[cl*24 + k2];
            am = fmaf(xr[2*k2],   w.x, am);
            am = fmaf(xr[2*k2+1], w.y, am);
            ag = fmaf(xr[2*k2],   w.z, ag);
            ag = fmaf(xr[2*k2+1], w.w, ag);
        }
        float xin = (c < C0) ? xr[c*3 + 2] : 0.0f;
        float val = (am + xin) * (1.0f / (1.0f + __expf(-ag)));
        sx[cl*129 + nl] = val;
    }
    __syncthreads();

    int base = ((b*TP + t)*Nn + n0)*C1c + ch*16;
    for (int idx = tid; idx < 128*16; idx += 128) {
        int n2 = idx >> 4, cl = idx & 15;
        g_xg[base + n2*64 + cl] = sx[cl*129 + n2];
    }
}

// ---------------------------------------------------------------------------
// Kernel B: grid 41 blocks x 256 threads.
// ---------------------------------------------------------------------------
__global__ void kB(const float* __restrict__ adj,
                   const float* __restrict__ lnw,
                   const float* __restrict__ lnb,
                   const float* __restrict__ Wh,
                   const float* __restrict__ ah) {
    int tid = threadIdx.x;
    int bid = blockIdx.x;

    if (bid < 32) {
        int w = tid >> 5, lane = tid & 31;
        int i = bid*8 + w;
        int cnt = 0;
        #pragma unroll
        for (int cc = 0; cc < 8; cc++) {
            float av = adj[i*Nn + cc*32 + lane];
            unsigned m = __ballot_sync(0xffffffffu, av > 0.0f);
            if (av > 0.0f) {
                int pos = cnt + __popc(m & ((1u << lane) - 1u));
                if (pos < DMAX) g_nbr[i*DMAX + pos] = cc*32 + lane;
            }
            cnt += __popc(m);
        }
        if (lane == 0) g_deg[i] = (cnt > DMAX) ? DMAX : cnt;
    } else if (bid < 40) {
        int p = bid - 32;
        #pragma unroll
        for (int k = 0; k < 8; k++) {
            int idx = p*2048 + k*256 + tid;
            int c = idx >> 8, n2 = idx & 255;
            g_lnwT[idx] = lnw[n2*C2c + c];
            g_lnbT[idx] = lnb[n2*C2c + c];
        }
    } else {
        #pragma unroll
        for (int r = 0; r < 4; r++) {
            int id = tid + r*256;
            int j = id & 15, c = id >> 4;     // j = h*2 + half
            int h = j >> 1, half = j & 1;
            const float* wr = Wh + (h*64 + c)*64;
            const float* ar = ah + h*128 + half*64;
            float s = 0.0f;
            #pragma unroll
            for (int d2 = 0; d2 < 64; d2++) s = fmaf(wr[d2], ar[d2], s);
            g_vT[c*16 + j] = s;
        }
    }
}

// ---------------------------------------------------------------------------
// Kernel Agg: all-8-head GAT + residual -> x_s.
// grid (2, TP, B) = 160 blocks, 512 threads (16 warps), 128 rows/block,
// 8 rows/warp. e-stage split by head-group across thread halves.
// ---------------------------------------------------------------------------
__global__ void kAgg() {
    extern __shared__ float sm[];
    float* sxg   = sm;                 // 256*66 = 16896
    float* se2   = sxg + 16896;        // 8*256 = 2048
    float* se1   = se2 + 2048;         // 8*128 = 1024 (own rows)
    float* svT   = se1 + 1024;         // 64*16 = 1024
    float* stash = svT + 1024;         // 16 warps * 864 (768 p + 96 nbr)
    int tid = threadIdx.x;
    int q = blockIdx.x, t = blockIdx.y, b = blockIdx.z;
    int base = ((b*TP + t)*Nn)*C1c;
    int i0 = q*128;

    for (int idx = tid; idx < Nn*C1c/4; idx += 512) {
        float4 v = ((const float4*)(g_xg + base))[idx];
        int n2 = idx >> 4, cq = (idx & 15) * 4;
        float* p = sxg + n2*66 + cq;
        p[0] = v.x; p[1] = v.y; p[2] = v.z; p[3] = v.w;
    }
    for (int idx = tid; idx < 1024; idx += 512) svT[idx] = g_vT[idx];
    __syncthreads();

    {   // e-stage: head-group split. hg = tid>>8 handles heads hg*4..hg*4+3.
        int n = tid & 255, hg = tid >> 8;
        float a1[4], a2[4];
        #pragma unroll
        for (int h = 0; h < 4; h++) { a1[h] = 0.0f; a2[h] = 0.0f; }
        #pragma unroll 8
        for (int c = 0; c < 64; c++) {
            float xv = sxg[n*66 + c];
            const float4* vq = (const float4*)(svT + c*16 + hg*8);
            float4 q0 = vq[0], q1 = vq[1];
            a1[0] = fmaf(xv, q0.x, a1[0]); a2[0] = fmaf(xv, q0.y, a2[0]);
            a1[1] = fmaf(xv, q0.z, a1[1]); a2[1] = fmaf(xv, q0.w, a2[1]);
            a1[2] = fmaf(xv, q1.x, a1[2]); a2[2] = fmaf(xv, q1.y, a2[2]);
            a1[3] = fmaf(xv, q1.z, a1[3]); a2[3] = fmaf(xv, q1.w, a2[3]);
        }
        #pragma unroll
        for (int h = 0; h < 4; h++) se2[(hg*4 + h)*256 + n] = a2[h];
        if (n >= i0 && n < i0 + 128) {
            #pragma unroll
            for (int h = 0; h < 4; h++) se1[(hg*4 + h)*128 + (n - i0)] = a1[h];
        }
    }
    __syncthreads();

    int w = tid >> 5, lane = tid & 31;
    float* sp  = stash + w*864;
    int*   snb = (int*)(sp + 768);
    int c0 = 2*lane;

    for (int rr = 0; rr < 8; rr++) {
        int il = w*8 + rr;
        int i = i0 + il;
        int d = g_deg[i];
        for (int k = lane; k < d; k += 32) snb[k] = g_nbr[i*DMAX + k];
        __syncwarp();

        float e1v[8];
        #pragma unroll
        for (int h = 0; h < 8; h++) e1v[h] = se1[h*128 + il];

        // stage A: unnormalized attention weights p[k][h]
        #pragma unroll
        for (int kk = 0; kk < 3; kk++) {
            int k = lane + kk*32;
            if (k < d) {
                int j = snb[k];
                float4 pa, pb;
                {
                    float s0 = e1v[0] + se2[0*256 + j];
                    float s1 = e1v[1] + se2[1*256 + j];
                    float s2 = e1v[2] + se2[2*256 + j];
                    float s3 = e1v[3] + se2[3*256 + j];
                    pa.x = __expf(fmaxf(s0, ALPHA*s0));
                    pa.y = __expf(fmaxf(s1, ALPHA*s1));
                    pa.z = __expf(fmaxf(s2, ALPHA*s2));
                    pa.w = __expf(fmaxf(s3, ALPHA*s3));
                }
                {
                    float s4 = e1v[4] + se2[4*256 + j];
                    float s5 = e1v[5] + se2[5*256 + j];
                    float s6 = e1v[6] + se2[6*256 + j];
                    float s7 = e1v[7] + se2[7*256 + j];
                    pb.x = __expf(fmaxf(s4, ALPHA*s4));
                    pb.y = __expf(fmaxf(s5, ALPHA*s5));
                    pb.z = __expf(fmaxf(s6, ALPHA*s6));
                    pb.w = __expf(fmaxf(s7, ALPHA*s7));
                }
                *(float4*)&sp[k*8]     = pa;
                *(float4*)&sp[k*8 + 4] = pb;
            }
        }
        __syncwarp();

        // stage B: fused 8-head gather-aggregate + per-lane redundant sums
        float a[16];
        float S[8];
        #pragma unroll
        for (int u = 0; u < 16; u++) a[u] = 0.0f;
        #pragma unroll
        for (int h = 0; h < 8; h++) S[h] = 0.0f;

        int j = (d > 0) ? snb[0] : 0;
        for (int k = 0; k < d; k++) {
            int jn = (k + 1 < d) ? snb[k + 1] : 0;
            float4 pa = *(const float4*)&sp[k*8];
            float4 pb = *(const float4*)&sp[k*8 + 4];
            float2 xv = *(const float2*)&sxg[j*66 + c0];
            a[0]  = fmaf(pa.x, xv.x, a[0]);   a[1]  = fmaf(pa.x, xv.y, a[1]);
            a[2]  = fmaf(pa.y, xv.x, a[2]);   a[3]  = fmaf(pa.y, xv.y, a[3]);
            a[4]  = fmaf(pa.z, xv.x, a[4]);   a[5]  = fmaf(pa.z, xv.y, a[5]);
            a[6]  = fmaf(pa.w, xv.x, a[6]);   a[7]  = fmaf(pa.w, xv.y, a[7]);
            a[8]  = fmaf(pb.x, xv.x, a[8]);   a[9]  = fmaf(pb.x, xv.y, a[9]);
            a[10] = fmaf(pb.y, xv.x, a[10]);  a[11] = fmaf(pb.y, xv.y, a[11]);
            a[12] = fmaf(pb.z, xv.x, a[12]);  a[13] = fmaf(pb.z, xv.y, a[13]);
            a[14] = fmaf(pb.w, xv.x, a[14]);  a[15] = fmaf(pb.w, xv.y, a[15]);
            S[0] += pa.x; S[1] += pa.y; S[2] += pa.z; S[3] += pa.w;
            S[4] += pb.x; S[5] += pb.y; S[6] += pb.z; S[7] += pb.w;
            j = jn;
        }

        float rx = 0.0f, ry = 0.0f;
        #pragma unroll
        for (int h = 0; h < 8; h++) {
            float rs = 1.0f / S[h];
            rx += tanh_ap(a[2*h]     * rs);
            ry += tanh_ap(a[2*h + 1] * rs);
        }
        float2 x0 = *(const float2*)&sxg[i*66 + c0];
        float2 o;
        o.x = x0.x + rx * 0.125f;
        o.y = x0.y + ry * 0.125f;
        *(float2*)&g_xs[base + i*64 + c0] = o;
        __syncwarp();   // sp/snb reused next row
    }
}

// ---------------------------------------------------------------------------
// Kernel D1: conv2 + residual + relu + partial LN stats, t2-PAIRED.
// grid (T2/2, B, 4 cout-chunks) = 128 blocks, 512 threads:
// half = tid>>8 (8 couts), n = tid&255. Each thread computes 8 couts for
// t2a = 2*bx and t2b = t2a+1 (weights amortized 2x). 4 temporal slices.
// ---------------------------------------------------------------------------
__global__ void kD1(const float* __restrict__ w2, const float* __restrict__ b2) {
    extern __shared__ float sm[];
    float* sx2  = sm;            // 4*256*17 = 17408
    float* sw2a = sm + 17408;    // 4*48*16 = 3072
    __shared__ float red[64];
    int tid = threadIdx.x;
    int t2a = blockIdx.x*2, b = blockIdx.y, cs = blockIdx.z;
    int half = tid >> 8, n = tid & 255;
    int bT = b*TP + t2a;

    // weights for all 4 g-chunks, layout [g][ci*3+kt][16]
    for (int idx = tid; idx < 4*48*16; idx += 512) {
        int cout = idx & 15;
        int r = idx >> 4;        // 0..191
        int g = r / 48;
        int ck = r % 48;
        int ci = ck / 3, kt = ck % 3;
        sw2a[idx] = w2[(cs*16 + cout)*(C1c*KTc) + (g*16 + ci)*KTc + kt];
    }

    float acc[16];   // [0..7] t2a couts, [8..15] t2b couts
    #pragma unroll
    for (int cc = 0; cc < 8; cc++) {
        float bb = __ldg(b2 + cs*16 + half*8 + cc);
        acc[cc] = bb; acc[8 + cc] = bb;
    }

    int ci_s = tid & 15, nb0 = tid >> 4;     // staging coords (512 threads)

    #pragma unroll
    for (int g = 0; g < 4; g++) {
        __syncthreads();
        #pragma unroll
        for (int u = 0; u < 32; u++) {
            int linear = nb0 + 32*u;          // 0..1023
            int kt = linear >> 8, nn = linear & 255;
            sx2[(kt*256 + nn)*17 + ci_s] =
                g_xs[((bT + kt)*Nn + nn)*C1c + g*16 + ci_s];
        }
        __syncthreads();

        #pragma unroll 4
        for (int ci = 0; ci < 16; ci++) {
            #pragma unroll
            for (int kt = 0; kt < 3; kt++) {
                float xva = sx2[(kt*256 + n)*17 + ci];
                float xvb = sx2[((kt + 1)*256 + n)*17 + ci];
                const float4* wr = (const float4*)(sw2a + (g*48 + ci*3 + kt)*16 + half*8);
                float4 w0 = wr[0], w1v = wr[1];
                acc[0]  = fmaf(xva, w0.x,  acc[0]);
                acc[1]  = fmaf(xva, w0.y,  acc[1]);
                acc[2]  = fmaf(xva, w0.z,  acc[2]);
                acc[3]  = fmaf(xva, w0.w,  acc[3]);
                acc[4]  = fmaf(xva, w1v.x, acc[4]);
                acc[5]  = fmaf(xva, w1v.y, acc[5]);
                acc[6]  = fmaf(xva, w1v.z, acc[6]);
                acc[7]  = fmaf(xva, w1v.w, acc[7]);
                acc[8]  = fmaf(xvb, w0.x,  acc[8]);
                acc[9]  = fmaf(xvb, w0.y,  acc[9]);
                acc[10] = fmaf(xvb, w0.z,  acc[10]);
                acc[11] = fmaf(xvb, w0.w,  acc[11]);
                acc[12] = fmaf(xvb, w1v.x, acc[12]);
                acc[13] = fmaf(xvb, w1v.y, acc[13]);
                acc[14] = fmaf(xvb, w1v.z, acc[14]);
                acc[15] = fmaf(xvb, w1v.w, acc[15]);
            }
        }
        if (g == cs) {
            #pragma unroll
            for (int cc = 0; cc < 8; cc++) {
                acc[cc]     += sx2[(2*256 + n)*17 + half*8 + cc];
                acc[8 + cc] += sx2[(3*256 + n)*17 + half*8 + cc];
            }
        }
    }

    float lsA = 0.0f, lssA = 0.0f, lsB = 0.0f, lssB = 0.0f;
    #pragma unroll
    for (int cc = 0; cc < 8; cc++) {
        float va = fmaxf(acc[cc], 0.0f);
        float vb = fmaxf(acc[8 + cc], 0.0f);
        acc[cc] = va; acc[8 + cc] = vb;
        lsA += va; lssA = fmaf(va, va, lssA);
        lsB += vb; lssB = fmaf(vb, vb, lssB);
    }
    #pragma unroll
    for (int o = 16; o > 0; o >>= 1) {
        lsA  += __shfl_xor_sync(0xffffffffu, lsA,  o);
        lssA += __shfl_xor_sync(0xffffffffu, lssA, o);
        lsB  += __shfl_xor_sync(0xffffffffu, lsB,  o);
        lssB += __shfl_xor_sync(0xffffffffu, lssB, o);
    }
    int w = tid >> 5, lane = tid & 31;
    if (lane == 0) {
        red[w] = lsA; red[w + 16] = lssA;
        red[w + 32] = lsB; red[w + 48] = lssB;
    }
    __syncthreads();
    if (tid == 0) {
        float SA = 0, SSA = 0, SB = 0, SSB = 0;
        #pragma unroll
        for (int i = 0; i < 16; i++) {
            SA += red[i]; SSA += red[i + 16];
            SB += red[i + 32]; SSB += red[i + 48];
        }
        int btA = b*T2 + t2a;
        g_psum[(btA*4 + cs)*2]     = SA;
        g_psum[(btA*4 + cs)*2 + 1] = SSA;
        g_psum[((btA+1)*4 + cs)*2]     = SB;
        g_psum[((btA+1)*4 + cs)*2 + 1] = SSB;
    }

    int ybaseA = ((b*T2 + t2a)*C2c + cs*16 + half*8)*Nn;
    int ybaseB = ybaseA + C2c*Nn;
    #pragma unroll
    for (int cc = 0; cc < 8; cc++) {
        g_y[ybaseA + cc*Nn + n] = acc[cc];
        g_y[ybaseB + cc*Nn + n] = acc[8 + cc];
    }
}

// ---------------------------------------------------------------------------
// Kernel E: LayerNorm + transposed store. grid (T2, B, 4), 256 threads.
// ---------------------------------------------------------------------------
__global__ void kE(float* __restrict__ out) {
    int t2 = blockIdx.x, b = blockIdx.y, cs = blockIdx.z;
    int bt = b*T2 + t2;
    float S = 0.0f, SS = 0.0f;
    #pragma unroll
    for (int qq = 0; qq < 4; qq++) {
        S  += g_psum[(bt*4 + qq)*2];
        SS += g_psum[(bt*4 + qq)*2 + 1];
    }
    float mu   = S * (1.0f/16384.0f);
    float var  = SS * (1.0f/16384.0f) - mu*mu;
    float rstd = rsqrtf(var + 1e-5f);
    int n = threadIdx.x;
    #pragma unroll
    for (int cc = 0; cc < 16; cc++) {
        int c = cs*16 + cc;
        float yv = (g_y[(bt*C2c + c)*Nn + n] - mu) * rstd;
        out[((b*C2c + c)*T2 + t2)*Nn + n] =
            fmaf(yv, g_lnwT[c*Nn + n], g_lnbT[c*Nn + n]);
    }
}

// ---------------------------------------------------------------------------
extern "C" void kernel_launch(void* const* d_in, const int* in_sizes, int n_in,
                              void* d_out, int out_size) {
    const float* x   = (const float*)d_in[0];
    const float* adj = (const float*)d_in[1];
    const float* w1  = (const float*)d_in[2];
    const float* b1  = (const float*)d_in[3];
    const float* w2  = (const float*)d_in[4];
    const float* b2  = (const float*)d_in[5];
    const float* Wh  = (const float*)d_in[6];
    const float* ah  = (const float*)d_in[7];
    const float* lnw = (const float*)d_in[8];
    const float* lnb = (const float*)d_in[9];
    float* out = (float*)d_out;

    const int smA   = (6144 + 1536) * 4;                          // 30720
    const int smAgg = (16896 + 2048 + 1024 + 1024 + 16*864) * 4;  // 139264
    const int smD   = (17408 + 3072) * 4;                         // 81920
    cudaFuncSetAttribute(kA,   cudaFuncAttributeMaxDynamicSharedMemorySize, smA);
    cudaFuncSetAttribute(kAgg, cudaFuncAttributeMaxDynamicSharedMemorySize, smAgg);
    cudaFuncSetAttribute(kD1,  cudaFuncAttributeMaxDynamicSharedMemorySize, smD);

    kA<<<dim3(8, TP, Bn), 128, smA>>>(x, w1, b1);
    kB<<<41, 256>>>(adj, lnw, lnb, Wh, ah);
    kAgg<<<dim3(2, TP, Bn), 512, smAgg>>>();
    kD1<<<dim3(T2/2, Bn, 4), 512, smD>>>(w2, b2);
    kE<<<dim3(T2, Bn, 4), 256>>>(out);
}

// round 8
// speedup vs baseline: 3.4801x; 1.1784x over previous
#include <cuda_runtime.h>
#include <math.h>

#define Bn 8
#define C0 16
#define C1c 64
#define C2c 64
#define Tt 12
#define TP 10
#define T2 8
#define Nn 256
#define KTc 3
#define Hh 8
#define ALPHA 0.2f
#define DMAX 64
#define XSZ (Bn*TP*Nn*C1c)   // 1310720

// scratch (static device allocations — allowed)
__device__ float g_xg[XSZ];          // x_t1 in [b,t,n,c]
__device__ float g_xs[XSZ];          // x_t1 + gat -> x_s
__device__ float g_y[Bn*T2*C2c*Nn];  // conv2+relu output, [bt][c][n]
__device__ float g_psum[Bn*T2*4*2*2];// per (bt, cs, nhalf) partial LN sums
__device__ int   g_deg[Nn];
__device__ int   g_nbr[Nn*DMAX];
__device__ float g_vT[64*16];        // vT[c*16 + h*2+half]
__device__ float g_lnwT[C2c*Nn];
__device__ float g_lnbT[C2c*Nn];

__device__ __forceinline__ float tanh_ap(float x) {
    float y;
    asm("tanh.approx.f32 %0, %1;" : "=f"(y) : "f"(x));
    return y;
}

// ---------------------------------------------------------------------------
// Kernel A: conv1 (KT=3) + GLU, grid (9, TP, B), 128 threads.
// q<8: conv octant (n-half, c-eighth). q==8: preprocessing work (former kB)
// running concurrently with the conv blocks: adjacency ballot-compaction,
// transposed LN params, v vectors.
// ---------------------------------------------------------------------------
__global__ void kA(const float* __restrict__ x,
                   const float* __restrict__ w1,
                   const float* __restrict__ b1,
                   const float* __restrict__ adj,
                   const float* __restrict__ lnw,
                   const float* __restrict__ lnb,
                   const float* __restrict__ Wh,
                   const float* __restrict__ ah) {
    extern __shared__ float sm[];
    int tid = threadIdx.x;
    int q = blockIdx.x, t = blockIdx.y, b = blockIdx.z;

    if (q == 8) {   // ---- preprocessing slice (80 slots, 41 used) ----
        int slot = t*8 + b;
        int w = tid >> 5, lane = tid & 31;
        if (slot < 32) {
            #pragma unroll
            for (int rr = 0; rr < 2; rr++) {
                int i = slot*8 + rr*4 + w;
                int cnt = 0;
                #pragma unroll
                for (int cc = 0; cc < 8; cc++) {
                    float av = adj[i*Nn + cc*32 + lane];
                    unsigned m = __ballot_sync(0xffffffffu, av > 0.0f);
                    if (av > 0.0f) {
                        int pos = cnt + __popc(m & ((1u << lane) - 1u));
                        if (pos < DMAX) g_nbr[i*DMAX + pos] = cc*32 + lane;
                    }
                    cnt += __popc(m);
                }
                if (lane == 0) g_deg[i] = (cnt > DMAX) ? DMAX : cnt;
            }
        } else if (slot < 40) {
            int p = slot - 32;
            #pragma unroll
            for (int k = 0; k < 16; k++) {
                int idx = p*2048 + k*128 + tid;
                int c = idx >> 8, n2 = idx & 255;
                g_lnwT[idx] = lnw[n2*C2c + c];
                g_lnbT[idx] = lnb[n2*C2c + c];
            }
        } else if (slot == 40) {
            #pragma unroll
            for (int r = 0; r < 8; r++) {
                int id = tid + r*128;
                int j = id & 15, c = id >> 4;     // j = h*2 + half
                int h = j >> 1, half = j & 1;
                const float* wr = Wh + (h*64 + c)*64;
                const float* ar = ah + h*128 + half*64;
                float s = 0.0f;
                #pragma unroll
                for (int d2 = 0; d2 < 64; d2++) s = fmaf(wr[d2], ar[d2], s);
                g_vT[c*16 + j] = s;
            }
        }
        return;
    }

    // ---- conv1 + GLU ----
    float*  sx  = sm;                       // 48*128 = 6144 (reused as sxt 16*129)
    float4* swp = (float4*)(sm + 6144);     // 16*24 float4
    int nh = q & 1, ch = q >> 1;            // ch: 0..3 -> 16 couts
    int n0 = nh * 128;

    #pragma unroll
    for (int u = 0; u < 48; u++) {
        sx[u*128 + tid] = x[((b*C0 + u/3)*Tt + t + (u%3))*Nn + n0 + tid];
    }
    for (int idx = tid; idx < 16*24; idx += 128) {
        int cl = idx / 24, k2 = idx % 24;
        int c = ch*16 + cl;
        float4 v;
        v.x = w1[c*48 + 2*k2];
        v.y = w1[c*48 + 2*k2 + 1];
        v.z = w1[(c+64)*48 + 2*k2];
        v.w = w1[(c+64)*48 + 2*k2 + 1];
        swp[idx] = v;
    }
    __syncthreads();

    int nl = tid;
    float xr[48];
    #pragma unroll
    for (int k = 0; k < 48; k++) xr[k] = sx[k*128 + nl];
    __syncthreads();   // sx reused as sxt below

    #pragma unroll
    for (int cl = 0; cl < 16; cl++) {
        int c = ch*16 + cl;
        float am = __ldg(b1 + c);
        float ag = __ldg(b1 + c + 64);
        #pragma unroll
        for (int k2 = 0; k2 < 24; k2++) {
            float4 w = swp[cl*24 + k2];
            am = fmaf(xr[2*k2],   w.x, am);
            am = fmaf(xr[2*k2+1], w.y, am);
            ag = fmaf(xr[2*k2],   w.z, ag);
            ag = fmaf(xr[2*k2+1], w.w, ag);
        }
        float xin = (c < C0) ? xr[c*3 + 2] : 0.0f;
        float val = (am + xin) * (1.0f / (1.0f + __expf(-ag)));
        sx[cl*129 + nl] = val;
    }
    __syncthreads();

    int base = ((b*TP + t)*Nn + n0)*C1c + ch*16;
    for (int idx = tid; idx < 128*16; idx += 128) {
        int n2 = idx >> 4, cl = idx & 15;
        g_xg[base + n2*64 + cl] = sx[cl*129 + n2];
    }
}

// ---------------------------------------------------------------------------
// Kernel Agg: all-8-head GAT + residual -> x_s. grid (4, TP, B) = 320 blocks,
// 256 threads (8 warps, 8 rows/warp). S accumulated in stage A (per-lane
// partials + butterfly), gather loop is pure FMA+LDS, unrolled x2.
// ---------------------------------------------------------------------------
__global__ void kAgg() {
    extern __shared__ float sm[];
    float* sxg   = sm;                 // 256*66 = 16896
    float* se2   = sxg + 16896;        // 8*256 = 2048
    float* se1   = se2 + 2048;         // 8*64  = 512 (own rows)
    float* svT   = se1 + 512;          // 64*16 = 1024
    float* stash = svT + 1024;         // 8 warps * 576 (512 p + 64 nbr)
    int tid = threadIdx.x;
    int q = blockIdx.x, t = blockIdx.y, b = blockIdx.z;
    int base = ((b*TP + t)*Nn)*C1c;
    int i0 = q*64;

    for (int idx = tid; idx < Nn*C1c/4; idx += 256) {
        float4 v = ((const float4*)(g_xg + base))[idx];
        int n2 = idx >> 4, cq = (idx & 15) * 4;
        float* p = sxg + n2*66 + cq;
        p[0] = v.x; p[1] = v.y; p[2] = v.z; p[3] = v.w;
    }
    for (int idx = tid; idx < 1024; idx += 256) svT[idx] = g_vT[idx];
    __syncthreads();

    {   // e2 for all n, e1 for own 64 rows
        int n = tid;
        float a1[8], a2[8];
        #pragma unroll
        for (int h = 0; h < 8; h++) { a1[h] = 0.0f; a2[h] = 0.0f; }
        #pragma unroll 8
        for (int c = 0; c < 64; c++) {
            float xv = sxg[n*66 + c];
            const float4* vq = (const float4*)(svT + c*16);
            float4 q0 = vq[0], q1 = vq[1], q2 = vq[2], q3 = vq[3];
            a1[0] = fmaf(xv, q0.x, a1[0]); a2[0] = fmaf(xv, q0.y, a2[0]);
            a1[1] = fmaf(xv, q0.z, a1[1]); a2[1] = fmaf(xv, q0.w, a2[1]);
            a1[2] = fmaf(xv, q1.x, a1[2]); a2[2] = fmaf(xv, q1.y, a2[2]);
            a1[3] = fmaf(xv, q1.z, a1[3]); a2[3] = fmaf(xv, q1.w, a2[3]);
            a1[4] = fmaf(xv, q2.x, a1[4]); a2[4] = fmaf(xv, q2.y, a2[4]);
            a1[5] = fmaf(xv, q2.z, a1[5]); a2[5] = fmaf(xv, q2.w, a2[5]);
            a1[6] = fmaf(xv, q3.x, a1[6]); a2[6] = fmaf(xv, q3.y, a2[6]);
            a1[7] = fmaf(xv, q3.z, a1[7]); a2[7] = fmaf(xv, q3.w, a2[7]);
        }
        #pragma unroll
        for (int h = 0; h < 8; h++) se2[h*256 + n] = a2[h];
        if (n >= i0 && n < i0 + 64) {
            #pragma unroll
            for (int h = 0; h < 8; h++) se1[h*64 + (n - i0)] = a1[h];
        }
    }
    __syncthreads();

    int w = tid >> 5, lane = tid & 31;
    float* sp  = stash + w*576;
    int*   snb = (int*)(sp + 512);
    int c0 = 2*lane;

    for (int rr = 0; rr < 8; rr++) {
        int il = w*8 + rr;
        int i = i0 + il;
        int d = g_deg[i];
        if (lane < d) snb[lane] = g_nbr[i*DMAX + lane];
        if (lane + 32 < d) snb[lane + 32] = g_nbr[i*DMAX + lane + 32];
        __syncwarp();

        float e1v[8];
        #pragma unroll
        for (int h = 0; h < 8; h++) e1v[h] = se1[h*64 + il];

        // stage A: p[k][h] + per-lane partial sums S[h]
        float S[8];
        #pragma unroll
        for (int h = 0; h < 8; h++) S[h] = 0.0f;
        #pragma unroll
        for (int kk = 0; kk < 2; kk++) {
            int k = lane + kk*32;
            if (k < d) {
                int j = snb[k];
                float4 pa, pb;
                {
                    float s0 = e1v[0] + se2[0*256 + j];
                    float s1 = e1v[1] + se2[1*256 + j];
                    float s2 = e1v[2] + se2[2*256 + j];
                    float s3 = e1v[3] + se2[3*256 + j];
                    pa.x = __expf(fmaxf(s0, ALPHA*s0));
                    pa.y = __expf(fmaxf(s1, ALPHA*s1));
                    pa.z = __expf(fmaxf(s2, ALPHA*s2));
                    pa.w = __expf(fmaxf(s3, ALPHA*s3));
                }
                {
                    float s4 = e1v[4] + se2[4*256 + j];
                    float s5 = e1v[5] + se2[5*256 + j];
                    float s6 = e1v[6] + se2[6*256 + j];
                    float s7 = e1v[7] + se2[7*256 + j];
                    pb.x = __expf(fmaxf(s4, ALPHA*s4));
                    pb.y = __expf(fmaxf(s5, ALPHA*s5));
                    pb.z = __expf(fmaxf(s6, ALPHA*s6));
                    pb.w = __expf(fmaxf(s7, ALPHA*s7));
                }
                *(float4*)&sp[k*8]     = pa;
                *(float4*)&sp[k*8 + 4] = pb;
                S[0] += pa.x; S[1] += pa.y; S[2] += pa.z; S[3] += pa.w;
                S[4] += pb.x; S[5] += pb.y; S[6] += pb.z; S[7] += pb.w;
            }
        }
        // close S with butterfly reductions (all lanes get full sums)
        #pragma unroll
        for (int o = 16; o > 0; o >>= 1) {
            #pragma unroll
            for (int h = 0; h < 8; h++)
                S[h] += __shfl_xor_sync(0xffffffffu, S[h], o);
        }
        __syncwarp();

        // stage B: fused 8-head gather-aggregate, unrolled x2
        float a[16];
        #pragma unroll
        for (int u = 0; u < 16; u++) a[u] = 0.0f;

        int k = 0;
        for (; k + 2 <= d; k += 2) {
            int ja = snb[k], jb = snb[k+1];
            float4 pa0 = *(const float4*)&sp[k*8];
            float4 pa1 = *(const float4*)&sp[k*8 + 4];
            float4 pb0 = *(const float4*)&sp[(k+1)*8];
            float4 pb1 = *(const float4*)&sp[(k+1)*8 + 4];
            float2 xa = *(const float2*)&sxg[ja*66 + c0];
            float2 xb = *(const float2*)&sxg[jb*66 + c0];
            a[0]  = fmaf(pa0.x, xa.x, a[0]);   a[1]  = fmaf(pa0.x, xa.y, a[1]);
            a[2]  = fmaf(pa0.y, xa.x, a[2]);   a[3]  = fmaf(pa0.y, xa.y, a[3]);
            a[4]  = fmaf(pa0.z, xa.x, a[4]);   a[5]  = fmaf(pa0.z, xa.y, a[5]);
            a[6]  = fmaf(pa0.w, xa.x, a[6]);   a[7]  = fmaf(pa0.w, xa.y, a[7]);
            a[8]  = fmaf(pa1.x, xa.x, a[8]);   a[9]  = fmaf(pa1.x, xa.y, a[9]);
            a[10] = fmaf(pa1.y, xa.x, a[10]);  a[11] = fmaf(pa1.y, xa.y, a[11]);
            a[12] = fmaf(pa1.z, xa.x, a[12]);  a[13] = fmaf(pa1.z, xa.y, a[13]);
            a[14] = fmaf(pa1.w, xa.x, a[14]);  a[15] = fmaf(pa1.w, xa.y, a[15]);
            a[0]  = fmaf(pb0.x, xb.x, a[0]);   a[1]  = fmaf(pb0.x, xb.y, a[1]);
            a[2]  = fmaf(pb0.y, xb.x, a[2]);   a[3]  = fmaf(pb0.y, xb.y, a[3]);
            a[4]  = fmaf(pb0.z, xb.x, a[4]);   a[5]  = fmaf(pb0.z, xb.y, a[5]);
            a[6]  = fmaf(pb0.w, xb.x, a[6]);   a[7]  = fmaf(pb0.w, xb.y, a[7]);
            a[8]  = fmaf(pb1.x, xb.x, a[8]);   a[9]  = fmaf(pb1.x, xb.y, a[9]);
            a[10] = fmaf(pb1.y, xb.x, a[10]);  a[11] = fmaf(pb1.y, xb.y, a[11]);
            a[12] = fmaf(pb1.z, xb.x, a[12]);  a[13] = fmaf(pb1.z, xb.y, a[13]);
            a[14] = fmaf(pb1.w, xb.x, a[14]);  a[15] = fmaf(pb1.w, xb.y, a[15]);
        }
        if (k < d) {
            int j = snb[k];
            float4 p0 = *(const float4*)&sp[k*8];
            float4 p1 = *(const float4*)&sp[k*8 + 4];
            float2 xv = *(const float2*)&sxg[j*66 + c0];
            a[0]  = fmaf(p0.x, xv.x, a[0]);   a[1]  = fmaf(p0.x, xv.y, a[1]);
            a[2]  = fmaf(p0.y, xv.x, a[2]);   a[3]  = fmaf(p0.y, xv.y, a[3]);
            a[4]  = fmaf(p0.z, xv.x, a[4]);   a[5]  = fmaf(p0.z, xv.y, a[5]);
            a[6]  = fmaf(p0.w, xv.x, a[6]);   a[7]  = fmaf(p0.w, xv.y, a[7]);
            a[8]  = fmaf(p1.x, xv.x, a[8]);   a[9]  = fmaf(p1.x, xv.y, a[9]);
            a[10] = fmaf(p1.y, xv.x, a[10]);  a[11] = fmaf(p1.y, xv.y, a[11]);
            a[12] = fmaf(p1.z, xv.x, a[12]);  a[13] = fmaf(p1.z, xv.y, a[13]);
            a[14] = fmaf(p1.w, xv.x, a[14]);  a[15] = fmaf(p1.w, xv.y, a[15]);
        }

        float rx = 0.0f, ry = 0.0f;
        #pragma unroll
        for (int h = 0; h < 8; h++) {
            float rs = 1.0f / S[h];
            rx += tanh_ap(a[2*h]     * rs);
            ry += tanh_ap(a[2*h + 1] * rs);
        }
        float2 x0 = *(const float2*)&sxg[i*66 + c0];
        float2 o;
        o.x = x0.x + rx * 0.125f;
        o.y = x0.y + ry * 0.125f;
        *(float2*)&g_xs[base + i*64 + c0] = o;
        __syncwarp();   // sp/snb reused next row
    }
}

// ---------------------------------------------------------------------------
// Kernel D1: conv2 + residual + relu + partial LN stats, t2-paired, n-split.
// grid (8, B, 4): bx = t2pair*2 + nhalf. 256 threads: half = tid>>7 (8 couts),
// nl = tid&127. smem 47KB -> 4 blocks/SM, 256 blocks = 1 wave.
// ---------------------------------------------------------------------------
__global__ void kD1(const float* __restrict__ w2, const float* __restrict__ b2) {
    extern __shared__ float sm[];
    float* sx2  = sm;            // 4*128*17 = 8704
    float* sw2a = sm + 8704;     // 4*48*16 = 3072
    __shared__ float red[32];
    int tid = threadIdx.x;
    int t2p = blockIdx.x >> 1, nh = blockIdx.x & 1;
    int b = blockIdx.y, cs = blockIdx.z;
    int half = tid >> 7, nl = tid & 127;
    int t2a = t2p*2;
    int bT = b*TP + t2a;
    int n0 = nh*128;

    // weights for all 4 g-chunks, layout [g][ci*3+kt][16]
    for (int idx = tid; idx < 4*48*16; idx += 256) {
        int cout = idx & 15;
        int r = idx >> 4;        // 0..191
        int g = r / 48;
        int ck = r % 48;
        int ci = ck / 3, kt = ck % 3;
        sw2a[idx] = w2[(cs*16 + cout)*(C1c*KTc) + (g*16 + ci)*KTc + kt];
    }

    float acc[16];   // [0..7] t2a couts, [8..15] t2b couts
    #pragma unroll
    for (int cc = 0; cc < 8; cc++) {
        float bb = __ldg(b2 + cs*16 + half*8 + cc);
        acc[cc] = bb; acc[8 + cc] = bb;
    }

    int ci_s = tid & 15, r0 = tid >> 4;      // staging coords

    #pragma unroll
    for (int g = 0; g < 4; g++) {
        __syncthreads();
        #pragma unroll
        for (int u = 0; u < 32; u++) {
            int linear = r0 + 16*u;           // 0..511
            int kt = linear >> 7, nn = linear & 127;
            sx2[(kt*128 + nn)*17 + ci_s] =
                g_xs[((bT + kt)*Nn + n0 + nn)*C1c + g*16 + ci_s];
        }
        __syncthreads();

        #pragma unroll 4
        for (int ci = 0; ci < 16; ci++) {
            #pragma unroll
            for (int kt = 0; kt < 3; kt++) {
                float xva = sx2[(kt*128 + nl)*17 + ci];
                float xvb = sx2[((kt + 1)*128 + nl)*17 + ci];
                const float4* wr = (const float4*)(sw2a + (g*48 + ci*3 + kt)*16 + half*8);
                float4 w0 = wr[0], w1v = wr[1];
                acc[0]  = fmaf(xva, w0.x,  acc[0]);
                acc[1]  = fmaf(xva, w0.y,  acc[1]);
                acc[2]  = fmaf(xva, w0.z,  acc[2]);
                acc[3]  = fmaf(xva, w0.w,  acc[3]);
                acc[4]  = fmaf(xva, w1v.x, acc[4]);
                acc[5]  = fmaf(xva, w1v.y, acc[5]);
                acc[6]  = fmaf(xva, w1v.z, acc[6]);
                acc[7]  = fmaf(xva, w1v.w, acc[7]);
                acc[8]  = fmaf(xvb, w0.x,  acc[8]);
                acc[9]  = fmaf(xvb, w0.y,  acc[9]);
                acc[10] = fmaf(xvb, w0.z,  acc[10]);
                acc[11] = fmaf(xvb, w0.w,  acc[11]);
                acc[12] = fmaf(xvb, w1v.x, acc[12]);
                acc[13] = fmaf(xvb, w1v.y, acc[13]);
                acc[14] = fmaf(xvb, w1v.z, acc[14]);
                acc[15] = fmaf(xvb, w1v.w, acc[15]);
            }
        }
        if (g == cs) {
            #pragma unroll
            for (int cc = 0; cc < 8; cc++) {
                acc[cc]     += sx2[(2*128 + nl)*17 + half*8 + cc];
                acc[8 + cc] += sx2[(3*128 + nl)*17 + half*8 + cc];
            }
        }
    }

    float lsA = 0.0f, lssA = 0.0f, lsB = 0.0f, lssB = 0.0f;
    #pragma unroll
    for (int cc = 0; cc < 8; cc++) {
        float va = fmaxf(acc[cc], 0.0f);
        float vb = fmaxf(acc[8 + cc], 0.0f);
        acc[cc] = va; acc[8 + cc] = vb;
        lsA += va; lssA = fmaf(va, va, lssA);
        lsB += vb; lssB = fmaf(vb, vb, lssB);
    }
    #pragma unroll
    for (int o = 16; o > 0; o >>= 1) {
        lsA  += __shfl_xor_sync(0xffffffffu, lsA,  o);
        lssA += __shfl_xor_sync(0xffffffffu, lssA, o);
        lsB  += __shfl_xor_sync(0xffffffffu, lsB,  o);
        lssB += __shfl_xor_sync(0xffffffffu, lssB, o);
    }
    int w = tid >> 5, lane = tid & 31;
    if (lane == 0) {
        red[w] = lsA; red[w + 8] = lssA;
        red[w + 16] = lsB; red[w + 24] = lssB;
    }
    __syncthreads();
    if (tid == 0) {
        float SA = 0, SSA = 0, SB = 0, SSB = 0;
        #pragma unroll
        for (int i = 0; i < 8; i++) {
            SA += red[i]; SSA += red[i + 8];
            SB += red[i + 16]; SSB += red[i + 24];
        }
        int btA = b*T2 + t2a;
        g_psum[((btA*4 + cs)*2 + nh)*2]     = SA;
        g_psum[((btA*4 + cs)*2 + nh)*2 + 1] = SSA;
        g_psum[(((btA+1)*4 + cs)*2 + nh)*2]     = SB;
        g_psum[(((btA+1)*4 + cs)*2 + nh)*2 + 1] = SSB;
    }

    int ybaseA = ((b*T2 + t2a)*C2c + cs*16 + half*8)*Nn + n0;
    int ybaseB = ybaseA + C2c*Nn;
    #pragma unroll
    for (int cc = 0; cc < 8; cc++) {
        g_y[ybaseA + cc*Nn + nl] = acc[cc];
        g_y[ybaseB + cc*Nn + nl] = acc[8 + cc];
    }
}

// ---------------------------------------------------------------------------
// Kernel E: LayerNorm + transposed store. grid (T2, B, 4), 256 threads.
// ---------------------------------------------------------------------------
__global__ void kE(float* __restrict__ out) {
    int t2 = blockIdx.x, b = blockIdx.y, cs = blockIdx.z;
    int bt = b*T2 + t2;
    float S = 0.0f, SS = 0.0f;
    #pragma unroll
    for (int qq = 0; qq < 8; qq++) {
        S  += g_psum[(bt*4)*4 + qq*2];
        SS += g_psum[(bt*4)*4 + qq*2 + 1];
    }
    float mu   = S * (1.0f/16384.0f);
    float var  = SS * (1.0f/16384.0f) - mu*mu;
    float rstd = rsqrtf(var + 1e-5f);
    int n = threadIdx.x;
    #pragma unroll
    for (int cc = 0; cc < 16; cc++) {
        int c = cs*16 + cc;
        float yv = (g_y[(bt*C2c + c)*Nn + n] - mu) * rstd;
        out[((b*C2c + c)*T2 + t2)*Nn + n] =
            fmaf(yv, g_lnwT[c*Nn + n], g_lnbT[c*Nn + n]);
    }
}

// ---------------------------------------------------------------------------
extern "C" void kernel_launch(void* const* d_in, const int* in_sizes, int n_in,
                              void* d_out, int out_size) {
    const float* x   = (const float*)d_in[0];
    const float* adj = (const float*)d_in[1];
    const float* w1  = (const float*)d_in[2];
    const float* b1  = (const float*)d_in[3];
    const float* w2  = (const float*)d_in[4];
    const float* b2  = (const float*)d_in[5];
    const float* Wh  = (const float*)d_in[6];
    const float* ah  = (const float*)d_in[7];
    const float* lnw = (const float*)d_in[8];
    const float* lnb = (const float*)d_in[9];
    float* out = (float*)d_out;

    const int smA   = (6144 + 1536) * 4;                        // 30720
    const int smAgg = (16896 + 2048 + 512 + 1024 + 8*576) * 4;  // 100352
    const int smD   = (8704 + 3072) * 4;                        // 47104
    cudaFuncSetAttribute(kA,   cudaFuncAttributeMaxDynamicSharedMemorySize, smA);
    cudaFuncSetAttribute(kAgg, cudaFuncAttributeMaxDynamicSharedMemorySize, smAgg);
    cudaFuncSetAttribute(kD1,  cudaFuncAttributeMaxDynamicSharedMemorySize, smD);

    kA<<<dim3(9, TP, Bn), 128, smA>>>(x, w1, b1, adj, lnw, lnb, Wh, ah);
    kAgg<<<dim3(4, TP, Bn), 256, smAgg>>>();
    kD1<<<dim3(8, Bn, 4), 256, smD>>>(w2, b2);
    kE<<<dim3(T2, Bn, 4), 256>>>(out);
}

// round 9
// speedup vs baseline: 3.5548x; 1.0215x over previous
#include <cuda_runtime.h>
#include <math.h>

#define Bn 8
#define C0 16
#define C1c 64
#define C2c 64
#define Tt 12
#define TP 10
#define T2 8
#define Nn 256
#define KTc 3
#define Hh 8
#define ALPHA 0.2f
#define DMAX 64
#define XSZ (Bn*TP*Nn*C1c)   // 1310720

// scratch (static device allocations — allowed)
__device__ float g_xg[XSZ];          // x_t1 in [b,t,n,c]
__device__ float g_xs[XSZ];          // x_t1 + gat -> x_s
__device__ float g_y[Bn*T2*C2c*Nn];  // conv2+relu output, [bt][c][n]
__device__ float g_psum[Bn*T2*4*2*2];// per (bt, cs, nhalf) partial LN sums
__device__ int   g_deg[Nn];
__device__ unsigned char g_nbr8[Nn*DMAX];
__device__ float g_vT[64*16];        // vT[c*16 + h*2+half]
__device__ float g_lnwT[C2c*Nn];
__device__ float g_lnbT[C2c*Nn];

__device__ __forceinline__ float tanh_ap(float x) {
    float y;
    asm("tanh.approx.f32 %0, %1;" : "=f"(y) : "f"(x));
    return y;
}

// ---------------------------------------------------------------------------
// Kernel A: conv1 (KT=3) + GLU, grid (9, TP, B), 128 threads.
// q<8: conv octant. q==8: preprocessing (adjacency byte-lists, LN transpose,
// v vectors) running concurrently.
// ---------------------------------------------------------------------------
__global__ void kA(const float* __restrict__ x,
                   const float* __restrict__ w1,
                   const float* __restrict__ b1,
                   const float* __restrict__ adj,
                   const float* __restrict__ lnw,
                   const float* __restrict__ lnb,
                   const float* __restrict__ Wh,
                   const float* __restrict__ ah) {
    extern __shared__ float sm[];
    int tid = threadIdx.x;
    int q = blockIdx.x, t = blockIdx.y, b = blockIdx.z;

    if (q == 8) {   // ---- preprocessing slice ----
        int slot = t*8 + b;
        int w = tid >> 5, lane = tid & 31;
        if (slot < 32) {
            #pragma unroll
            for (int rr = 0; rr < 2; rr++) {
                int i = slot*8 + rr*4 + w;
                int cnt = 0;
                #pragma unroll
                for (int cc = 0; cc < 8; cc++) {
                    float av = adj[i*Nn + cc*32 + lane];
                    unsigned m = __ballot_sync(0xffffffffu, av > 0.0f);
                    if (av > 0.0f) {
                        int pos = cnt + __popc(m & ((1u << lane) - 1u));
                        if (pos < DMAX)
                            g_nbr8[i*DMAX + pos] = (unsigned char)(cc*32 + lane);
                    }
                    cnt += __popc(m);
                }
                if (lane == 0) g_deg[i] = (cnt > DMAX) ? DMAX : cnt;
            }
        } else if (slot < 40) {
            int p = slot - 32;
            #pragma unroll
            for (int k = 0; k < 16; k++) {
                int idx = p*2048 + k*128 + tid;
                int c = idx >> 8, n2 = idx & 255;
                g_lnwT[idx] = lnw[n2*C2c + c];
                g_lnbT[idx] = lnb[n2*C2c + c];
            }
        } else if (slot == 40) {
            #pragma unroll
            for (int r = 0; r < 8; r++) {
                int id = tid + r*128;
                int j = id & 15, c = id >> 4;     // j = h*2 + half
                int h = j >> 1, half = j & 1;
                const float* wr = Wh + (h*64 + c)*64;
                const float* ar = ah + h*128 + half*64;
                float s = 0.0f;
                #pragma unroll
                for (int d2 = 0; d2 < 64; d2++) s = fmaf(wr[d2], ar[d2], s);
                g_vT[c*16 + j] = s;
            }
        }
        return;
    }

    // ---- conv1 + GLU ----
    float*  sx  = sm;                       // 48*128 = 6144 (reused as sxt 16*129)
    float4* swp = (float4*)(sm + 6144);     // 16*24 float4
    int nh = q & 1, ch = q >> 1;
    int n0 = nh * 128;

    #pragma unroll
    for (int u = 0; u < 48; u++) {
        sx[u*128 + tid] = x[((b*C0 + u/3)*Tt + t + (u%3))*Nn + n0 + tid];
    }
    for (int idx = tid; idx < 16*24; idx += 128) {
        int cl = idx / 24, k2 = idx % 24;
        int c = ch*16 + cl;
        float4 v;
        v.x = w1[c*48 + 2*k2];
        v.y = w1[c*48 + 2*k2 + 1];
        v.z = w1[(c+64)*48 + 2*k2];
        v.w = w1[(c+64)*48 + 2*k2 + 1];
        swp[idx] = v;
    }
    __syncthreads();

    int nl = tid;
    float xr[48];
    #pragma unroll
    for (int k = 0; k < 48; k++) xr[k] = sx[k*128 + nl];
    __syncthreads();

    #pragma unroll
    for (int cl = 0; cl < 16; cl++) {
        int c = ch*16 + cl;
        float am = __ldg(b1 + c);
        float ag = __ldg(b1 + c + 64);
        #pragma unroll
        for (int k2 = 0; k2 < 24; k2++) {
            float4 w = swp[cl*24 + k2];
            am = fmaf(xr[2*k2],   w.x, am);
            am = fmaf(xr[2*k2+1], w.y, am);
            ag = fmaf(xr[2*k2],   w.z, ag);
            ag = fmaf(xr[2*k2+1], w.w, ag);
        }
        float xin = (c < C0) ? xr[c*3 + 2] : 0.0f;
        float val = (am + xin) * (1.0f / (1.0f + __expf(-ag)));
        sx[cl*129 + nl] = val;
    }
    __syncthreads();

    int base = ((b*TP + t)*Nn + n0)*C1c + ch*16;
    for (int idx = tid; idx < 128*16; idx += 128) {
        int n2 = idx >> 4, cl = idx & 15;
        g_xg[base + n2*64 + cl] = sx[cl*129 + n2];
    }
}

// ---------------------------------------------------------------------------
// Kernel Agg: all-8-head GAT + residual -> x_s. grid (4, TP, B), 256 threads.
// HALF-WARP PER ROW: each warp processes 2 rows concurrently (4 pairs).
// sxg group-XOR swizzle (stride 64) gives conflict-free aligned LDS128 gather.
// ---------------------------------------------------------------------------
__global__ void kAgg() {
    extern __shared__ float sm[];
    float* sxg   = sm;                 // 256*64 = 16384 (swizzled groups)
    float* se2   = sxg + 16384;        // 8*256 = 2048
    float* se1   = se2 + 2048;         // 8*64  = 512
    float* svT   = se1 + 512;          // 64*16 = 1024
    float* stash = svT + 1024;         // 8 warps * 1056 (2x512 p + 128B nbr)
    int tid = threadIdx.x;
    int q = blockIdx.x, t = blockIdx.y, b = blockIdx.z;
    int base = ((b*TP + t)*Nn)*C1c;
    int i0 = q*64;

    for (int idx = tid; idx < 4096; idx += 256) {
        float4 v = ((const float4*)(g_xg + base))[idx];
        int n2 = idx >> 4, g = idx & 15;
        *(float4*)&sxg[n2*64 + ((g ^ (n2 & 15)) << 2)] = v;
    }
    for (int idx = tid; idx < 1024; idx += 256) svT[idx] = g_vT[idx];
    __syncthreads();

    {   // e-stage: e2 for all n, e1 for own 64 rows
        int n = tid;
        int sw = n & 15;
        float a1[8], a2[8];
        #pragma unroll
        for (int h = 0; h < 8; h++) { a1[h] = 0.0f; a2[h] = 0.0f; }
        #pragma unroll
        for (int g = 0; g < 16; g++) {
            float4 xv = *(const float4*)&sxg[n*64 + ((g ^ sw) << 2)];
            float xs[4] = {xv.x, xv.y, xv.z, xv.w};
            #pragma unroll
            for (int e = 0; e < 4; e++) {
                float xe = xs[e];
                const float4* vq = (const float4*)(svT + (4*g + e)*16);
                float4 q0 = vq[0], q1 = vq[1], q2 = vq[2], q3 = vq[3];
                a1[0] = fmaf(xe, q0.x, a1[0]); a2[0] = fmaf(xe, q0.y, a2[0]);
                a1[1] = fmaf(xe, q0.z, a1[1]); a2[1] = fmaf(xe, q0.w, a2[1]);
                a1[2] = fmaf(xe, q1.x, a1[2]); a2[2] = fmaf(xe, q1.y, a2[2]);
                a1[3] = fmaf(xe, q1.z, a1[3]); a2[3] = fmaf(xe, q1.w, a2[3]);
                a1[4] = fmaf(xe, q2.x, a1[4]); a2[4] = fmaf(xe, q2.y, a2[4]);
                a1[5] = fmaf(xe, q2.z, a1[5]); a2[5] = fmaf(xe, q2.w, a2[5]);
                a1[6] = fmaf(xe, q3.x, a1[6]); a2[6] = fmaf(xe, q3.y, a2[6]);
                a1[7] = fmaf(xe, q3.z, a1[7]); a2[7] = fmaf(xe, q3.w, a2[7]);
            }
        }
        #pragma unroll
        for (int h = 0; h < 8; h++) se2[h*256 + n] = a2[h];
        if (n >= i0 && n < i0 + 64) {
            #pragma unroll
            for (int h = 0; h < 8; h++) se1[h*64 + (n - i0)] = a1[h];
        }
    }
    __syncthreads();

    int w = tid >> 5, lane = tid & 31;
    int rowSel = lane >> 4, hl = lane & 15;
    float* spw   = stash + w*1056;          // [spA 512][spB 512][nbr 128B]
    float* spMy  = spw + rowSel*512;
    unsigned char* snbMy = (unsigned char*)(spw + 1024) + rowSel*64;

    for (int rr = 0; rr < 4; rr++) {
        int il = w*8 + rr*2 + rowSel;
        int i = i0 + il;
        int d = g_deg[i];
        int dOther = __shfl_xor_sync(0xffffffffu, d, 16);
        int kmax = (d > dOther) ? d : dOther;

        float e1v[8];
        #pragma unroll
        for (int h = 0; h < 8; h++) e1v[h] = se1[h*64 + il];

        // stage A: slots k = hl + 16s, both rows in parallel
        float S[8];
        #pragma unroll
        for (int h = 0; h < 8; h++) S[h] = 0.0f;
        #pragma unroll
        for (int s = 0; s < 4; s++) {
            int k = hl + s*16;
            float4 pa = {0.f,0.f,0.f,0.f}, pb = {0.f,0.f,0.f,0.f};
            int j = 0;
            if (k < d) {
                j = g_nbr8[i*DMAX + k];
                float s0 = e1v[0] + se2[0*256 + j];
                float s1 = e1v[1] + se2[1*256 + j];
                float s2 = e1v[2] + se2[2*256 + j];
                float s3 = e1v[3] + se2[3*256 + j];
                pa.x = __expf(fmaxf(s0, ALPHA*s0));
                pa.y = __expf(fmaxf(s1, ALPHA*s1));
                pa.z = __expf(fmaxf(s2, ALPHA*s2));
                pa.w = __expf(fmaxf(s3, ALPHA*s3));
                float s4 = e1v[4] + se2[4*256 + j];
                float s5 = e1v[5] + se2[5*256 + j];
                float s6 = e1v[6] + se2[6*256 + j];
                float s7 = e1v[7] + se2[7*256 + j];
                pb.x = __expf(fmaxf(s4, ALPHA*s4));
                pb.y = __expf(fmaxf(s5, ALPHA*s5));
                pb.z = __expf(fmaxf(s6, ALPHA*s6));
                pb.w = __expf(fmaxf(s7, ALPHA*s7));
            }
            snbMy[k] = (unsigned char)j;
            *(float4*)&spMy[k*8]     = pa;
            *(float4*)&spMy[k*8 + 4] = pb;
            S[0] += pa.x; S[1] += pa.y; S[2] += pa.z; S[3] += pa.w;
            S[4] += pb.x; S[5] += pb.y; S[6] += pb.z; S[7] += pb.w;
        }
        // half-warp butterfly: full sums per row
        #pragma unroll
        for (int o = 8; o > 0; o >>= 1) {
            #pragma unroll
            for (int h = 0; h < 8; h++)
                S[h] += __shfl_xor_sync(0xffffffffu, S[h], o);
        }
        __syncwarp();

        // stage B: gather, 4 logical channels per lane (cbase = 4*hl)
        float a[32];
        #pragma unroll
        for (int u = 0; u < 32; u++) a[u] = 0.0f;

        int k = 0;
        for (; k + 2 <= kmax; k += 2) {
            int ja = snbMy[k], jb = snbMy[k+1];
            float4 pa0 = *(const float4*)&spMy[k*8];
            float4 pa1 = *(const float4*)&spMy[k*8 + 4];
            float4 pb0 = *(const float4*)&spMy[(k+1)*8];
            float4 pb1 = *(const float4*)&spMy[(k+1)*8 + 4];
            float4 xa = *(const float4*)&sxg[ja*64 + ((hl ^ (ja & 15)) << 2)];
            float4 xb = *(const float4*)&sxg[jb*64 + ((hl ^ (jb & 15)) << 2)];
            float xav[4] = {xa.x, xa.y, xa.z, xa.w};
            float xbv[4] = {xb.x, xb.y, xb.z, xb.w};
            float pav[8] = {pa0.x, pa0.y, pa0.z, pa0.w, pa1.x, pa1.y, pa1.z, pa1.w};
            float pbv[8] = {pb0.x, pb0.y, pb0.z, pb0.w, pb1.x, pb1.y, pb1.z, pb1.w};
            #pragma unroll
            for (int h = 0; h < 8; h++) {
                #pragma unroll
                for (int e = 0; e < 4; e++) {
                    a[h*4+e] = fmaf(pav[h], xav[e], a[h*4+e]);
                    a[h*4+e] = fmaf(pbv[h], xbv[e], a[h*4+e]);
                }
            }
        }
        if (k < kmax) {
            int j = snbMy[k];
            float4 p0 = *(const float4*)&spMy[k*8];
            float4 p1 = *(const float4*)&spMy[k*8 + 4];
            float4 xv = *(const float4*)&sxg[j*64 + ((hl ^ (j & 15)) << 2)];
            float xsv[4] = {xv.x, xv.y, xv.z, xv.w};
            float pv[8] = {p0.x, p0.y, p0.z, p0.w, p1.x, p1.y, p1.z, p1.w};
            #pragma unroll
            for (int h = 0; h < 8; h++)
                #pragma unroll
                for (int e = 0; e < 4; e++)
                    a[h*4+e] = fmaf(pv[h], xsv[e], a[h*4+e]);
        }

        float rs[8];
        #pragma unroll
        for (int h = 0; h < 8; h++) rs[h] = 1.0f / S[h];
        float r[4] = {0.0f, 0.0f, 0.0f, 0.0f};
        #pragma unroll
        for (int h = 0; h < 8; h++) {
            #pragma unroll
            for (int e = 0; e < 4; e++)
                r[e] += tanh_ap(a[h*4+e] * rs[h]);
        }
        float4 x0 = *(const float4*)&sxg[i*64 + ((hl ^ (i & 15)) << 2)];
        float4 o;
        o.x = x0.x + r[0]*0.125f;
        o.y = x0.y + r[1]*0.125f;
        o.z = x0.z + r[2]*0.125f;
        o.w = x0.w + r[3]*0.125f;
        *(float4*)&g_xs[base + i*64 + 4*hl] = o;
        __syncwarp();   // stash reused next pair
    }
}

// ---------------------------------------------------------------------------
// Kernel D1: conv2 + residual + relu + partial LN stats, t2-paired, n-split.
// grid (8, B, 4), 256 threads.
// ---------------------------------------------------------------------------
__global__ void kD1(const float* __restrict__ w2, const float* __restrict__ b2) {
    extern __shared__ float sm[];
    float* sx2  = sm;            // 4*128*17 = 8704
    float* sw2a = sm + 8704;     // 4*48*16 = 3072
    __shared__ float red[32];
    int tid = threadIdx.x;
    int t2p = blockIdx.x >> 1, nh = blockIdx.x & 1;
    int b = blockIdx.y, cs = blockIdx.z;
    int half = tid >> 7, nl = tid & 127;
    int t2a = t2p*2;
    int bT = b*TP + t2a;
    int n0 = nh*128;

    for (int idx = tid; idx < 4*48*16; idx += 256) {
        int cout = idx & 15;
        int r = idx >> 4;
        int g = r / 48;
        int ck = r % 48;
        int ci = ck / 3, kt = ck % 3;
        sw2a[idx] = w2[(cs*16 + cout)*(C1c*KTc) + (g*16 + ci)*KTc + kt];
    }

    float acc[16];
    #pragma unroll
    for (int cc = 0; cc < 8; cc++) {
        float bb = __ldg(b2 + cs*16 + half*8 + cc);
        acc[cc] = bb; acc[8 + cc] = bb;
    }

    int ci_s = tid & 15, r0 = tid >> 4;

    #pragma unroll
    for (int g = 0; g < 4; g++) {
        __syncthreads();
        #pragma unroll
        for (int u = 0; u < 32; u++) {
            int linear = r0 + 16*u;
            int kt = linear >> 7, nn = linear & 127;
            sx2[(kt*128 + nn)*17 + ci_s] =
                g_xs[((bT + kt)*Nn + n0 + nn)*C1c + g*16 + ci_s];
        }
        __syncthreads();

        #pragma unroll 4
        for (int ci = 0; ci < 16; ci++) {
            #pragma unroll
            for (int kt = 0; kt < 3; kt++) {
                float xva = sx2[(kt*128 + nl)*17 + ci];
                float xvb = sx2[((kt + 1)*128 + nl)*17 + ci];
                const float4* wr = (const float4*)(sw2a + (g*48 + ci*3 + kt)*16 + half*8);
                float4 w0 = wr[0], w1v = wr[1];
                acc[0]  = fmaf(xva, w0.x,  acc[0]);
                acc[1]  = fmaf(xva, w0.y,  acc[1]);
                acc[2]  = fmaf(xva, w0.z,  acc[2]);
                acc[3]  = fmaf(xva, w0.w,  acc[3]);
                acc[4]  = fmaf(xva, w1v.x, acc[4]);
                acc[5]  = fmaf(xva, w1v.y, acc[5]);
                acc[6]  = fmaf(xva, w1v.z, acc[6]);
                acc[7]  = fmaf(xva, w1v.w, acc[7]);
                acc[8]  = fmaf(xvb, w0.x,  acc[8]);
                acc[9]  = fmaf(xvb, w0.y,  acc[9]);
                acc[10] = fmaf(xvb, w0.z,  acc[10]);
                acc[11] = fmaf(xvb, w0.w,  acc[11]);
                acc[12] = fmaf(xvb, w1v.x, acc[12]);
                acc[13] = fmaf(xvb, w1v.y, acc[13]);
                acc[14] = fmaf(xvb, w1v.z, acc[14]);
                acc[15] = fmaf(xvb, w1v.w, acc[15]);
            }
        }
        if (g == cs) {
            #pragma unroll
            for (int cc = 0; cc < 8; cc++) {
                acc[cc]     += sx2[(2*128 + nl)*17 + half*8 + cc];
                acc[8 + cc] += sx2[(3*128 + nl)*17 + half*8 + cc];
            }
        }
    }

    float lsA = 0.0f, lssA = 0.0f, lsB = 0.0f, lssB = 0.0f;
    #pragma unroll
    for (int cc = 0; cc < 8; cc++) {
        float va = fmaxf(acc[cc], 0.0f);
        float vb = fmaxf(acc[8 + cc], 0.0f);
        acc[cc] = va; acc[8 + cc] = vb;
        lsA += va; lssA = fmaf(va, va, lssA);
        lsB += vb; lssB = fmaf(vb, vb, lssB);
    }
    #pragma unroll
    for (int o = 16; o > 0; o >>= 1) {
        lsA  += __shfl_xor_sync(0xffffffffu, lsA,  o);
        lssA += __shfl_xor_sync(0xffffffffu, lssA, o);
        lsB  += __shfl_xor_sync(0xffffffffu, lsB,  o);
        lssB += __shfl_xor_sync(0xffffffffu, lssB, o);
    }
    int w = tid >> 5, lane = tid & 31;
    if (lane == 0) {
        red[w] = lsA; red[w + 8] = lssA;
        red[w + 16] = lsB; red[w + 24] = lssB;
    }
    __syncthreads();
    if (tid == 0) {
        float SA = 0, SSA = 0, SB = 0, SSB = 0;
        #pragma unroll
        for (int i = 0; i < 8; i++) {
            SA += red[i]; SSA += red[i + 8];
            SB += red[i + 16]; SSB += red[i + 24];
        }
        int btA = b*T2 + t2a;
        g_psum[((btA*4 + cs)*2 + nh)*2]     = SA;
        g_psum[((btA*4 + cs)*2 + nh)*2 + 1] = SSA;
        g_psum[(((btA+1)*4 + cs)*2 + nh)*2]     = SB;
        g_psum[(((btA+1)*4 + cs)*2 + nh)*2 + 1] = SSB;
    }

    int ybaseA = ((b*T2 + t2a)*C2c + cs*16 + half*8)*Nn + n0;
    int ybaseB = ybaseA + C2c*Nn;
    #pragma unroll
    for (int cc = 0; cc < 8; cc++) {
        g_y[ybaseA + cc*Nn + nl] = acc[cc];
        g_y[ybaseB + cc*Nn + nl] = acc[8 + cc];
    }
}

// ---------------------------------------------------------------------------
// Kernel E: LayerNorm + transposed store. grid (T2, B, 8), 256 threads.
// ---------------------------------------------------------------------------
__global__ void kE(float* __restrict__ out) {
    int t2 = blockIdx.x, b = blockIdx.y, cs = blockIdx.z;  // cs: 8 couts
    int bt = b*T2 + t2;
    float S = 0.0f, SS = 0.0f;
    #pragma unroll
    for (int qq = 0; qq < 8; qq++) {
        S  += g_psum[bt*16 + qq*2];
        SS += g_psum[bt*16 + qq*2 + 1];
    }
    float mu   = S * (1.0f/16384.0f);
    float var  = SS * (1.0f/16384.0f) - mu*mu;
    float rstd = rsqrtf(var + 1e-5f);
    int n = threadIdx.x;
    #pragma unroll
    for (int cc = 0; cc < 8; cc++) {
        int c = cs*8 + cc;
        float yv = (g_y[(bt*C2c + c)*Nn + n] - mu) * rstd;
        out[((b*C2c + c)*T2 + t2)*Nn + n] =
            fmaf(yv, g_lnwT[c*Nn + n], g_lnbT[c*Nn + n]);
    }
}

// ---------------------------------------------------------------------------
extern "C" void kernel_launch(void* const* d_in, const int* in_sizes, int n_in,
                              void* d_out, int out_size) {
    const float* x   = (const float*)d_in[0];
    const float* adj = (const float*)d_in[1];
    const float* w1  = (const float*)d_in[2];
    const float* b1  = (const float*)d_in[3];
    const float* w2  = (const float*)d_in[4];
    const float* b2  = (const float*)d_in[5];
    const float* Wh  = (const float*)d_in[6];
    const float* ah  = (const float*)d_in[7];
    const float* lnw = (const float*)d_in[8];
    const float* lnb = (const float*)d_in[9];
    float* out = (float*)d_out;

    const int smA   = (6144 + 1536) * 4;                        // 30720
    const int smAgg = (16384 + 2048 + 512 + 1024 + 8*1056) * 4; // 113664
    const int smD   = (8704 + 3072) * 4;                        // 47104
    cudaFuncSetAttribute(kA,   cudaFuncAttributeMaxDynamicSharedMemorySize, smA);
    cudaFuncSetAttribute(kAgg, cudaFuncAttributeMaxDynamicSharedMemorySize, smAgg);
    cudaFuncSetAttribute(kD1,  cudaFuncAttributeMaxDynamicSharedMemorySize, smD);

    kA<<<dim3(9, TP, Bn), 128, smA>>>(x, w1, b1, adj, lnw, lnb, Wh, ah);
    kAgg<<<dim3(4, TP, Bn), 256, smAgg>>>();
    kD1<<<dim3(8, Bn, 4), 256, smD>>>(w2, b2);
    kE<<<dim3(T2, Bn, 8), 256>>>(out);
}